// round 1
// baseline (speedup 1.0000x reference)
#include <cuda_runtime.h>
#include <math.h>

#define V_ 4
#define N_ 1536
#define D_ 256
#define HEADS_ 4
#define DH_ 64
#define KTOP 32
#define M_ (V_*N_)    /* 6144 */
#define E3_ (3*D_)    /* 768  */

// ---------------- scratch (static device globals; no runtime allocation) ----------------
__device__ float g_qkv[M_*E3_];
__device__ float g_o[M_*D_];
__device__ float g_aligned[M_*D_];
__device__ float g_Qn[M_*D_];
__device__ float g_Kn[M_*D_];
__device__ float g_Vn[M_*D_];
__device__ float g_meanPart[V_*8*D_];
__device__ float g_meanV[V_*D_];
__device__ int   g_idx[V_*V_*N_*KTOP];

// ---------------- NT GEMM: C[m,e] = sum_k A[m,k]*B[e,k] (+ epilogue) ----------------
// MODE 0: +bias        MODE 1: aligned = alphas[v]*(acc+bias) + (1-alphas[v])*H   MODE 2: plain
#define BM 128
#define BN 64
#define BK 16

template<int MODE>
__global__ void __launch_bounds__(256) gemm_nt(
    const float* __restrict__ A, const float* __restrict__ B, float* __restrict__ Cout,
    const float* __restrict__ bias, const float* __restrict__ alphas,
    const float* __restrict__ Hin, int K, int aStrideZ, int bStrideZ)
{
    __shared__ float As[BK][BM];
    __shared__ float Bs[BK][BN];

    A    += (size_t)blockIdx.z * aStrideZ;
    Cout += (size_t)blockIdx.z * aStrideZ;   // valid: mode2 has E==K so C z-stride == A z-stride
    B    += (size_t)blockIdx.z * bStrideZ;

    const int E = gridDim.x * BN;
    const int tid = threadIdx.x;
    const int ty = tid >> 4, tx = tid & 15;
    const int mBase = blockIdx.y * BM;
    const int eBase = blockIdx.x * BN;

    float acc[8][4];
#pragma unroll
    for (int i = 0; i < 8; ++i)
#pragma unroll
        for (int j = 0; j < 4; ++j) acc[i][j] = 0.f;

    for (int kk = 0; kk < K; kk += BK) {
#pragma unroll
        for (int it = 0; it < 2; ++it) {
            int li = tid + it * 256;
            int r = li >> 2, c4 = li & 3;
            float4 t = *reinterpret_cast<const float4*>(A + (size_t)(mBase + r) * K + kk + c4 * 4);
            As[c4*4+0][r] = t.x; As[c4*4+1][r] = t.y; As[c4*4+2][r] = t.z; As[c4*4+3][r] = t.w;
        }
        {
            int r = tid >> 2, c4 = tid & 3;
            float4 t = *reinterpret_cast<const float4*>(B + (size_t)(eBase + r) * K + kk + c4 * 4);
            Bs[c4*4+0][r] = t.x; Bs[c4*4+1][r] = t.y; Bs[c4*4+2][r] = t.z; Bs[c4*4+3][r] = t.w;
        }
        __syncthreads();
#pragma unroll
        for (int kq = 0; kq < BK; ++kq) {
            float4 a0 = *reinterpret_cast<const float4*>(&As[kq][ty*8]);
            float4 a1 = *reinterpret_cast<const float4*>(&As[kq][ty*8+4]);
            float4 b0 = *reinterpret_cast<const float4*>(&Bs[kq][tx*4]);
            float a[8] = {a0.x, a0.y, a0.z, a0.w, a1.x, a1.y, a1.z, a1.w};
            float b[4] = {b0.x, b0.y, b0.z, b0.w};
#pragma unroll
            for (int i = 0; i < 8; ++i)
#pragma unroll
                for (int j = 0; j < 4; ++j)
                    acc[i][j] = fmaf(a[i], b[j], acc[i][j]);
        }
        __syncthreads();
    }

#pragma unroll
    for (int i = 0; i < 8; ++i) {
        int row = mBase + ty * 8 + i;
#pragma unroll
        for (int j = 0; j < 4; ++j) {
            int col = eBase + tx * 4 + j;
            float val = acc[i][j];
            if (MODE == 0) val += bias[col];
            if (MODE == 1) {
                int v = row / N_;
                float al = alphas[v];
                val = al * (val + bias[col]) + (1.f - al) * Hin[(size_t)row * D_ + col];
            }
            Cout[(size_t)row * E + col] = val;
        }
    }
}

// ---------------- per-(n,h) 4x4 view attention; o = softmax(qk^T/8) v ----------------
__global__ void attn_kernel(const float* __restrict__ qkv, float* __restrict__ o)
{
    int gw = (blockIdx.x * blockDim.x + threadIdx.x) >> 5;
    int lane = threadIdx.x & 31;
    if (gw >= N_ * HEADS_) return;
    int n = gw >> 2;
    int h = gw & 3;

    float q[4][2], k[4][2], v[4][2];
#pragma unroll
    for (int s = 0; s < 4; ++s) {
        size_t base = ((size_t)s * N_ + n) * E3_ + h * DH_ + lane;
        q[s][0] = qkv[base];          q[s][1] = qkv[base + 32];
        k[s][0] = qkv[base + D_];     k[s][1] = qkv[base + D_ + 32];
        v[s][0] = qkv[base + 2*D_];   v[s][1] = qkv[base + 2*D_ + 32];
    }
    float att[4][4];
#pragma unroll
    for (int s = 0; s < 4; ++s)
#pragma unroll
        for (int t = 0; t < 4; ++t) {
            float p = q[s][0]*k[t][0] + q[s][1]*k[t][1];
#pragma unroll
            for (int off = 16; off; off >>= 1) p += __shfl_xor_sync(0xffffffffu, p, off);
            att[s][t] = p * 0.125f;
        }
#pragma unroll
    for (int s = 0; s < 4; ++s) {
        float mx = fmaxf(fmaxf(att[s][0], att[s][1]), fmaxf(att[s][2], att[s][3]));
        float e0 = expf(att[s][0] - mx), e1 = expf(att[s][1] - mx);
        float e2 = expf(att[s][2] - mx), e3 = expf(att[s][3] - mx);
        float inv = 1.f / (e0 + e1 + e2 + e3);
        float w0 = e0*inv, w1 = e1*inv, w2 = e2*inv, w3 = e3*inv;
        float o0 = w0*v[0][0] + w1*v[1][0] + w2*v[2][0] + w3*v[3][0];
        float o1 = w0*v[0][1] + w1*v[1][1] + w2*v[2][1] + w3*v[3][1];
        size_t ob = ((size_t)s * N_ + n) * D_ + h * DH_ + lane;
        o[ob] = o0; o[ob + 32] = o1;
    }
}

// ---------------- top-32 of each off-diagonal C row + mask (C_hat>0) ----------------
__global__ void __launch_bounds__(128) topk_kernel(const float* __restrict__ C, int* __restrict__ outIdx)
{
    int n = blockIdx.x;
    int pid = blockIdx.y;              // 0..11 off-diagonal pairs
    int p = pid / 3;
    int qo = pid % 3;
    int q = qo + (qo >= p ? 1 : 0);
    const float* row = C + (((size_t)p * V_ + q) * N_ + n) * (size_t)N_;

    __shared__ float sv[N_];
    __shared__ unsigned long long wbest[4];
    __shared__ int selIdx[KTOP];
    __shared__ float selVal[KTOP];
    __shared__ float rsum;

    int tid = threadIdx.x, lane = tid & 31, warp = tid >> 5;

#pragma unroll
    for (int i = 0; i < 3; ++i) {        // 1536/(128*4) = 3 float4 per thread
        int li = tid + i * 128;
        float4 t = *reinterpret_cast<const float4*>(row + (size_t)li * 4);
        sv[li*4+0] = t.x; sv[li*4+1] = t.y; sv[li*4+2] = t.z; sv[li*4+3] = t.w;
    }
    __syncthreads();

    for (int it = 0; it < KTOP; ++it) {
        unsigned long long best = 0ull;
        for (int i = tid; i < N_; i += 128) {
            unsigned u = __float_as_uint(sv[i]);
            u = (u & 0x80000000u) ? ~u : (u | 0x80000000u);       // order-preserving key
            unsigned long long key = ((unsigned long long)u << 32) | (unsigned)(0xFFFFFFFFu - (unsigned)i);
            best = (key > best) ? key : best;
        }
#pragma unroll
        for (int off = 16; off; off >>= 1) {
            unsigned long long ot = __shfl_xor_sync(0xffffffffu, best, off);
            best = (ot > best) ? ot : best;
        }
        if (lane == 0) wbest[warp] = best;
        __syncthreads();
        if (tid == 0) {
            unsigned long long b = wbest[0];
            for (int w2 = 1; w2 < 4; ++w2) b = (wbest[w2] > b) ? wbest[w2] : b;
            int idx = (int)(0xFFFFFFFFu - (unsigned)(b & 0xFFFFFFFFull));
            selIdx[it] = idx;
            selVal[it] = sv[idx];
            sv[idx] = -3.402823e38f;
        }
        __syncthreads();
    }

    if (tid == 0) {
        float rs = 0.f;
        for (int j = 0; j < KTOP; ++j) rs += selVal[j];
        rsum = rs + 1e-12f;
    }
    __syncthreads();
    if (tid < KTOP) {
        bool m = (selVal[tid] / rsum) > 0.f;   // mask = C_hat > 0
        outIdx[(((size_t)p * V_ + q) * N_ + n) * KTOP + tid] = m ? selIdx[tid] : -1;
    }
}

// ---------------- Vn column means (diagonal / uniform-softmax contribution) ----------------
__global__ void meanv_part(const float* __restrict__ Vn, float* __restrict__ part)
{
    int v = blockIdx.x, s = blockIdx.y, d = threadIdx.x;
    int m0 = s * (N_ / 8);
    float acc = 0.f;
#pragma unroll 8
    for (int m = 0; m < N_ / 8; ++m)
        acc += Vn[((size_t)v * N_ + m0 + m) * D_ + d];
    part[((size_t)v * 8 + s) * D_ + d] = acc;
}

__global__ void meanv_reduce(const float* __restrict__ part, float* __restrict__ meanV)
{
    int v = blockIdx.x, d = threadIdx.x;
    float acc = 0.f;
#pragma unroll
    for (int s = 0; s < 8; ++s) acc += part[((size_t)v * 8 + s) * D_ + d];
    meanV[v * D_ + d] = acc * (1.0f / N_);
}

// ---------------- sparse neighbor attention + final fuse ----------------
__global__ void __launch_bounds__(256) nbr_final_kernel(
    const float* __restrict__ Qn, const float* __restrict__ Kn, const float* __restrict__ Vn,
    const float* __restrict__ meanV, const int* __restrict__ topIdx,
    const float* __restrict__ aligned, const float* __restrict__ Hin,
    const float* __restrict__ alpha_align, const float* __restrict__ beta,
    float* __restrict__ out)
{
    int n = blockIdx.x, p = blockIdx.y;
    int tid = threadIdx.x;
    int lane = tid & 31, warp = tid >> 5;

    __shared__ float qs[D_];
    __shared__ int   sidx[KTOP];
    __shared__ float sw[KTOP];
    __shared__ int   uniformFlag;

    qs[tid] = Qn[((size_t)p * N_ + n) * D_ + tid];
    float acc = meanV[p * D_ + tid];           // q == p: uniform softmax = mean of Vn[p]

    for (int qq = 0; qq < V_; ++qq) {
        if (qq == p) continue;
        __syncthreads();
        if (tid < KTOP) sidx[tid] = topIdx[(((size_t)p * V_ + qq) * N_ + n) * KTOP + tid];
        __syncthreads();

        // scores: each warp computes 4 of the 32 dot products
#pragma unroll
        for (int pass = 0; pass < 4; ++pass) {
            int j = pass * 8 + warp;
            int id = sidx[j];
            float s = 0.f;
            if (id >= 0) {
                const float* kr = Kn + ((size_t)qq * N_ + id) * D_;
#pragma unroll
                for (int c = 0; c < 8; ++c) s += qs[c * 32 + lane] * kr[c * 32 + lane];
#pragma unroll
                for (int off = 16; off; off >>= 1) s += __shfl_xor_sync(0xffffffffu, s, off);
            }
            if (lane == 0) sw[j] = (id >= 0) ? s * 0.0625f : -3.4e38f;   // /sqrt(256)
        }
        __syncthreads();

        // softmax over the (<=32) valid entries; invalid entries have weight exactly 0
        if (warp == 0) {
            int id = sidx[lane];
            float s = sw[lane];
            unsigned validMask = __ballot_sync(0xffffffffu, id >= 0);
            float mx = (id >= 0) ? s : -3.4e38f;
#pragma unroll
            for (int off = 16; off; off >>= 1) mx = fmaxf(mx, __shfl_xor_sync(0xffffffffu, mx, off));
            float e = (id >= 0) ? expf(s - mx) : 0.f;
            float sum = e;
#pragma unroll
            for (int off = 16; off; off >>= 1) sum += __shfl_xor_sync(0xffffffffu, sum, off);
            sw[lane] = (validMask == 0u) ? 0.f : e / sum;
            if (lane == 0) uniformFlag = (validMask == 0u);
        }
        __syncthreads();

        if (uniformFlag) {
            acc += meanV[qq * D_ + tid];       // all-masked row: uniform softmax over N
        } else {
#pragma unroll 4
            for (int j = 0; j < KTOP; ++j) {
                int id = sidx[j];
                if (id >= 0) acc += sw[j] * Vn[((size_t)qq * N_ + id) * D_ + tid];
            }
        }
    }

    float al = aligned[((size_t)p * N_ + n) * D_ + tid];
    float a  = 1.f / (1.f + expf(-alpha_align[0]));
    float f  = fmaxf(a * al + (1.f - a) * acc, 0.f);
    float b  = beta[0];
    out[((size_t)p * N_ + n) * D_ + tid] =
        b * Hin[((size_t)p * N_ + n) * D_ + tid] + (1.f - b) * f;
}

// ---------------- launch ----------------
extern "C" void kernel_launch(void* const* d_in, const int* in_sizes, int n_in,
                              void* d_out, int out_size)
{
    const float* H      = (const float*)d_in[0];
    const float* C      = (const float*)d_in[1];
    const float* WQ     = (const float*)d_in[2];
    const float* WK     = (const float*)d_in[3];
    const float* WV     = (const float*)d_in[4];
    const float* ipw    = (const float*)d_in[5];
    const float* ipb    = (const float*)d_in[6];
    const float* opw    = (const float*)d_in[7];
    const float* opb    = (const float*)d_in[8];
    const float* alphas = (const float*)d_in[9];
    const float* aal    = (const float*)d_in[10];
    const float* beta   = (const float*)d_in[11];
    float* out = (float*)d_out;

    float *qkv, *o, *aligned, *Qn, *Kn, *Vn, *meanP, *meanV;
    int* idx;
    cudaGetSymbolAddress((void**)&qkv,     g_qkv);
    cudaGetSymbolAddress((void**)&o,       g_o);
    cudaGetSymbolAddress((void**)&aligned, g_aligned);
    cudaGetSymbolAddress((void**)&Qn,      g_Qn);
    cudaGetSymbolAddress((void**)&Kn,      g_Kn);
    cudaGetSymbolAddress((void**)&Vn,      g_Vn);
    cudaGetSymbolAddress((void**)&meanP,   g_meanPart);
    cudaGetSymbolAddress((void**)&meanV,   g_meanV);
    cudaGetSymbolAddress((void**)&idx,     g_idx);

    // top-k depends only on C — launch first so it overlaps nothing but is ready early
    topk_kernel<<<dim3(N_, 12), 128>>>(C, idx);

    // qkv = H @ in_proj_w^T + b
    gemm_nt<0><<<dim3(E3_/BN, M_/BM, 1), 256>>>(H, ipw, qkv, ipb, nullptr, nullptr, D_, 0, 0);

    // per-(n,h) 4x4 view attention
    attn_kernel<<<(N_*HEADS_)/8, 256>>>(qkv, o);

    // aligned = alphas * (o @ out_proj^T + b) + (1-alphas) * H
    gemm_nt<1><<<dim3(D_/BN, M_/BM, 1), 256>>>(o, opw, aligned, opb, alphas, H, D_, 0, 0);

    // Qn/Kn/Vn = per-view aligned @ W^T
    gemm_nt<2><<<dim3(D_/BN, N_/BM, V_), 256>>>(aligned, WQ, Qn, nullptr, nullptr, nullptr, D_, N_*D_, D_*D_);
    gemm_nt<2><<<dim3(D_/BN, N_/BM, V_), 256>>>(aligned, WK, Kn, nullptr, nullptr, nullptr, D_, N_*D_, D_*D_);
    gemm_nt<2><<<dim3(D_/BN, N_/BM, V_), 256>>>(aligned, WV, Vn, nullptr, nullptr, nullptr, D_, N_*D_, D_*D_);

    // Vn column means
    meanv_part<<<dim3(V_, 8), 256>>>(Vn, meanP);
    meanv_reduce<<<V_, 256>>>(meanP, meanV);

    // sparse neighbor attention + final fusion
    nbr_final_kernel<<<dim3(N_, V_), 256>>>(Qn, Kn, Vn, meanV, idx, aligned, H, aal, beta, out);
}

// round 2
// speedup vs baseline: 1.0004x; 1.0004x over previous
#include <cuda_runtime.h>
#include <math.h>

#define V_ 4
#define N_ 1536
#define D_ 256
#define HEADS_ 4
#define DH_ 64
#define KTOP 32
#define M_ (V_*N_)    /* 6144 */
#define E3_ (3*D_)    /* 768  */

// ---------------- scratch (static device globals; no runtime allocation) ----------------
__device__ float g_qkv[M_*E3_];
__device__ float g_o[M_*D_];
__device__ float g_aligned[M_*D_];
__device__ float g_Qn[M_*D_];
__device__ float g_Kn[M_*D_];
__device__ float g_Vn[M_*D_];
__device__ float g_meanPart[V_*8*D_];
__device__ float g_meanV[V_*D_];
__device__ int   g_idx[V_*V_*N_*KTOP];

// ---------------- NT GEMM: C[m,e] = sum_k A[m,k]*B[e,k] (+ epilogue) ----------------
// MODE 0: +bias        MODE 1: aligned = alphas[v]*(acc+bias) + (1-alphas[v])*H   MODE 2: plain
#define BM 128
#define BN 64
#define BK 16

template<int MODE>
__global__ void __launch_bounds__(256) gemm_nt(
    const float* __restrict__ A, const float* __restrict__ B, float* __restrict__ Cout,
    const float* __restrict__ bias, const float* __restrict__ alphas,
    const float* __restrict__ Hin, int K, int aStrideZ, int bStrideZ)
{
    __shared__ float As[BK][BM];
    __shared__ float Bs[BK][BN];

    A    += (size_t)blockIdx.z * aStrideZ;
    Cout += (size_t)blockIdx.z * aStrideZ;   // valid: mode2 has E==K so C z-stride == A z-stride
    B    += (size_t)blockIdx.z * bStrideZ;

    const int E = gridDim.x * BN;
    const int tid = threadIdx.x;
    const int ty = tid >> 4, tx = tid & 15;
    const int mBase = blockIdx.y * BM;
    const int eBase = blockIdx.x * BN;

    float acc[8][4];
#pragma unroll
    for (int i = 0; i < 8; ++i)
#pragma unroll
        for (int j = 0; j < 4; ++j) acc[i][j] = 0.f;

    for (int kk = 0; kk < K; kk += BK) {
#pragma unroll
        for (int it = 0; it < 2; ++it) {
            int li = tid + it * 256;
            int r = li >> 2, c4 = li & 3;
            float4 t = *reinterpret_cast<const float4*>(A + (size_t)(mBase + r) * K + kk + c4 * 4);
            As[c4*4+0][r] = t.x; As[c4*4+1][r] = t.y; As[c4*4+2][r] = t.z; As[c4*4+3][r] = t.w;
        }
        {
            int r = tid >> 2, c4 = tid & 3;
            float4 t = *reinterpret_cast<const float4*>(B + (size_t)(eBase + r) * K + kk + c4 * 4);
            Bs[c4*4+0][r] = t.x; Bs[c4*4+1][r] = t.y; Bs[c4*4+2][r] = t.z; Bs[c4*4+3][r] = t.w;
        }
        __syncthreads();
#pragma unroll
        for (int kq = 0; kq < BK; ++kq) {
            float4 a0 = *reinterpret_cast<const float4*>(&As[kq][ty*8]);
            float4 a1 = *reinterpret_cast<const float4*>(&As[kq][ty*8+4]);
            float4 b0 = *reinterpret_cast<const float4*>(&Bs[kq][tx*4]);
            float a[8] = {a0.x, a0.y, a0.z, a0.w, a1.x, a1.y, a1.z, a1.w};
            float b[4] = {b0.x, b0.y, b0.z, b0.w};
#pragma unroll
            for (int i = 0; i < 8; ++i)
#pragma unroll
                for (int j = 0; j < 4; ++j)
                    acc[i][j] = fmaf(a[i], b[j], acc[i][j]);
        }
        __syncthreads();
    }

#pragma unroll
    for (int i = 0; i < 8; ++i) {
        int row = mBase + ty * 8 + i;
#pragma unroll
        for (int j = 0; j < 4; ++j) {
            int col = eBase + tx * 4 + j;
            float val = acc[i][j];
            if (MODE == 0) val += bias[col];
            if (MODE == 1) {
                int v = row / N_;
                float al = alphas[v];
                val = al * (val + bias[col]) + (1.f - al) * Hin[(size_t)row * D_ + col];
            }
            Cout[(size_t)row * E + col] = val;
        }
    }
}

// ---------------- per-(n,h) 4x4 view attention; o = softmax(qk^T/8) v ----------------
__global__ void attn_kernel(const float* __restrict__ qkv, float* __restrict__ o)
{
    int gw = (blockIdx.x * blockDim.x + threadIdx.x) >> 5;
    int lane = threadIdx.x & 31;
    if (gw >= N_ * HEADS_) return;
    int n = gw >> 2;
    int h = gw & 3;

    float q[4][2], k[4][2], v[4][2];
#pragma unroll
    for (int s = 0; s < 4; ++s) {
        size_t base = ((size_t)s * N_ + n) * E3_ + h * DH_ + lane;
        q[s][0] = qkv[base];          q[s][1] = qkv[base + 32];
        k[s][0] = qkv[base + D_];     k[s][1] = qkv[base + D_ + 32];
        v[s][0] = qkv[base + 2*D_];   v[s][1] = qkv[base + 2*D_ + 32];
    }
    float att[4][4];
#pragma unroll
    for (int s = 0; s < 4; ++s)
#pragma unroll
        for (int t = 0; t < 4; ++t) {
            float p = q[s][0]*k[t][0] + q[s][1]*k[t][1];
#pragma unroll
            for (int off = 16; off; off >>= 1) p += __shfl_xor_sync(0xffffffffu, p, off);
            att[s][t] = p * 0.125f;
        }
#pragma unroll
    for (int s = 0; s < 4; ++s) {
        float mx = fmaxf(fmaxf(att[s][0], att[s][1]), fmaxf(att[s][2], att[s][3]));
        float e0 = expf(att[s][0] - mx), e1 = expf(att[s][1] - mx);
        float e2 = expf(att[s][2] - mx), e3 = expf(att[s][3] - mx);
        float inv = 1.f / (e0 + e1 + e2 + e3);
        float w0 = e0*inv, w1 = e1*inv, w2 = e2*inv, w3 = e3*inv;
        float o0 = w0*v[0][0] + w1*v[1][0] + w2*v[2][0] + w3*v[3][0];
        float o1 = w0*v[0][1] + w1*v[1][1] + w2*v[2][1] + w3*v[3][1];
        size_t ob = ((size_t)s * N_ + n) * D_ + h * DH_ + lane;
        o[ob] = o0; o[ob + 32] = o1;
    }
}

// ---------------- top-32 of each off-diagonal C row + mask (C_hat>0) ----------------
__global__ void __launch_bounds__(128) topk_kernel(const float* __restrict__ C, int* __restrict__ outIdx)
{
    int n = blockIdx.x;
    int pid = blockIdx.y;              // 0..11 off-diagonal pairs
    int p = pid / 3;
    int qo = pid % 3;
    int q = qo + (qo >= p ? 1 : 0);
    const float* row = C + (((size_t)p * V_ + q) * N_ + n) * (size_t)N_;

    __shared__ float sv[N_];
    __shared__ unsigned long long wbest[4];
    __shared__ int selIdx[KTOP];
    __shared__ float selVal[KTOP];
    __shared__ float rsum;

    int tid = threadIdx.x, lane = tid & 31, warp = tid >> 5;

#pragma unroll
    for (int i = 0; i < 3; ++i) {        // 1536/(128*4) = 3 float4 per thread
        int li = tid + i * 128;
        float4 t = *reinterpret_cast<const float4*>(row + (size_t)li * 4);
        sv[li*4+0] = t.x; sv[li*4+1] = t.y; sv[li*4+2] = t.z; sv[li*4+3] = t.w;
    }
    __syncthreads();

    for (int it = 0; it < KTOP; ++it) {
        unsigned long long best = 0ull;
        for (int i = tid; i < N_; i += 128) {
            unsigned u = __float_as_uint(sv[i]);
            u = (u & 0x80000000u) ? ~u : (u | 0x80000000u);       // order-preserving key
            unsigned long long key = ((unsigned long long)u << 32) | (unsigned)(0xFFFFFFFFu - (unsigned)i);
            best = (key > best) ? key : best;
        }
#pragma unroll
        for (int off = 16; off; off >>= 1) {
            unsigned long long ot = __shfl_xor_sync(0xffffffffu, best, off);
            best = (ot > best) ? ot : best;
        }
        if (lane == 0) wbest[warp] = best;
        __syncthreads();
        if (tid == 0) {
            unsigned long long b = wbest[0];
            for (int w2 = 1; w2 < 4; ++w2) b = (wbest[w2] > b) ? wbest[w2] : b;
            int idx = (int)(0xFFFFFFFFu - (unsigned)(b & 0xFFFFFFFFull));
            selIdx[it] = idx;
            selVal[it] = sv[idx];
            sv[idx] = -3.402823e38f;
        }
        __syncthreads();
    }

    if (tid == 0) {
        float rs = 0.f;
        for (int j = 0; j < KTOP; ++j) rs += selVal[j];
        rsum = rs + 1e-12f;
    }
    __syncthreads();
    if (tid < KTOP) {
        bool m = (selVal[tid] / rsum) > 0.f;   // mask = C_hat > 0
        outIdx[(((size_t)p * V_ + q) * N_ + n) * KTOP + tid] = m ? selIdx[tid] : -1;
    }
}

// ---------------- Vn column means (diagonal / uniform-softmax contribution) ----------------
__global__ void meanv_part(const float* __restrict__ Vn, float* __restrict__ part)
{
    int v = blockIdx.x, s = blockIdx.y, d = threadIdx.x;
    int m0 = s * (N_ / 8);
    float acc = 0.f;
#pragma unroll 8
    for (int m = 0; m < N_ / 8; ++m)
        acc += Vn[((size_t)v * N_ + m0 + m) * D_ + d];
    part[((size_t)v * 8 + s) * D_ + d] = acc;
}

__global__ void meanv_reduce(const float* __restrict__ part, float* __restrict__ meanV)
{
    int v = blockIdx.x, d = threadIdx.x;
    float acc = 0.f;
#pragma unroll
    for (int s = 0; s < 8; ++s) acc += part[((size_t)v * 8 + s) * D_ + d];
    meanV[v * D_ + d] = acc * (1.0f / N_);
}

// ---------------- sparse neighbor attention + final fuse ----------------
__global__ void __launch_bounds__(256) nbr_final_kernel(
    const float* __restrict__ Qn, const float* __restrict__ Kn, const float* __restrict__ Vn,
    const float* __restrict__ meanV, const int* __restrict__ topIdx,
    const float* __restrict__ aligned, const float* __restrict__ Hin,
    const float* __restrict__ alpha_align, const float* __restrict__ beta,
    float* __restrict__ out)
{
    int n = blockIdx.x, p = blockIdx.y;
    int tid = threadIdx.x;
    int lane = tid & 31, warp = tid >> 5;

    __shared__ float qs[D_];
    __shared__ int   sidx[KTOP];
    __shared__ float sw[KTOP];
    __shared__ int   uniformFlag;

    qs[tid] = Qn[((size_t)p * N_ + n) * D_ + tid];
    float acc = meanV[p * D_ + tid];           // q == p: uniform softmax = mean of Vn[p]

    for (int qq = 0; qq < V_; ++qq) {
        if (qq == p) continue;
        __syncthreads();
        if (tid < KTOP) sidx[tid] = topIdx[(((size_t)p * V_ + qq) * N_ + n) * KTOP + tid];
        __syncthreads();

        // scores: each warp computes 4 of the 32 dot products
#pragma unroll
        for (int pass = 0; pass < 4; ++pass) {
            int j = pass * 8 + warp;
            int id = sidx[j];
            float s = 0.f;
            if (id >= 0) {
                const float* kr = Kn + ((size_t)qq * N_ + id) * D_;
#pragma unroll
                for (int c = 0; c < 8; ++c) s += qs[c * 32 + lane] * kr[c * 32 + lane];
#pragma unroll
                for (int off = 16; off; off >>= 1) s += __shfl_xor_sync(0xffffffffu, s, off);
            }
            if (lane == 0) sw[j] = (id >= 0) ? s * 0.0625f : -3.4e38f;   // /sqrt(256)
        }
        __syncthreads();

        // softmax over the (<=32) valid entries; invalid entries have weight exactly 0
        if (warp == 0) {
            int id = sidx[lane];
            float s = sw[lane];
            unsigned validMask = __ballot_sync(0xffffffffu, id >= 0);
            float mx = (id >= 0) ? s : -3.4e38f;
#pragma unroll
            for (int off = 16; off; off >>= 1) mx = fmaxf(mx, __shfl_xor_sync(0xffffffffu, mx, off));
            float e = (id >= 0) ? expf(s - mx) : 0.f;
            float sum = e;
#pragma unroll
            for (int off = 16; off; off >>= 1) sum += __shfl_xor_sync(0xffffffffu, sum, off);
            sw[lane] = (validMask == 0u) ? 0.f : e / sum;
            if (lane == 0) uniformFlag = (validMask == 0u);
        }
        __syncthreads();

        if (uniformFlag) {
            acc += meanV[qq * D_ + tid];       // all-masked row: uniform softmax over N
        } else {
#pragma unroll 4
            for (int j = 0; j < KTOP; ++j) {
                int id = sidx[j];
                if (id >= 0) acc += sw[j] * Vn[((size_t)qq * N_ + id) * D_ + tid];
            }
        }
    }

    float al = aligned[((size_t)p * N_ + n) * D_ + tid];
    float a  = 1.f / (1.f + expf(-alpha_align[0]));
    float f  = fmaxf(a * al + (1.f - a) * acc, 0.f);
    float b  = beta[0];
    out[((size_t)p * N_ + n) * D_ + tid] =
        b * Hin[((size_t)p * N_ + n) * D_ + tid] + (1.f - b) * f;
}

// ---------------- launch ----------------
extern "C" void kernel_launch(void* const* d_in, const int* in_sizes, int n_in,
                              void* d_out, int out_size)
{
    const float* H      = (const float*)d_in[0];
    const float* C      = (const float*)d_in[1];
    const float* WQ     = (const float*)d_in[2];
    const float* WK     = (const float*)d_in[3];
    const float* WV     = (const float*)d_in[4];
    const float* ipw    = (const float*)d_in[5];
    const float* ipb    = (const float*)d_in[6];
    const float* opw    = (const float*)d_in[7];
    const float* opb    = (const float*)d_in[8];
    const float* alphas = (const float*)d_in[9];
    const float* aal    = (const float*)d_in[10];
    const float* beta   = (const float*)d_in[11];
    float* out = (float*)d_out;

    float *qkv, *o, *aligned, *Qn, *Kn, *Vn, *meanP, *meanV;
    int* idx;
    cudaGetSymbolAddress((void**)&qkv,     g_qkv);
    cudaGetSymbolAddress((void**)&o,       g_o);
    cudaGetSymbolAddress((void**)&aligned, g_aligned);
    cudaGetSymbolAddress((void**)&Qn,      g_Qn);
    cudaGetSymbolAddress((void**)&Kn,      g_Kn);
    cudaGetSymbolAddress((void**)&Vn,      g_Vn);
    cudaGetSymbolAddress((void**)&meanP,   g_meanPart);
    cudaGetSymbolAddress((void**)&meanV,   g_meanV);
    cudaGetSymbolAddress((void**)&idx,     g_idx);

    // top-k depends only on C — launch first so it overlaps nothing but is ready early
    topk_kernel<<<dim3(N_, 12), 128>>>(C, idx);

    // qkv = H @ in_proj_w^T + b
    gemm_nt<0><<<dim3(E3_/BN, M_/BM, 1), 256>>>(H, ipw, qkv, ipb, nullptr, nullptr, D_, 0, 0);

    // per-(n,h) 4x4 view attention
    attn_kernel<<<(N_*HEADS_)/8, 256>>>(qkv, o);

    // aligned = alphas * (o @ out_proj^T + b) + (1-alphas) * H
    gemm_nt<1><<<dim3(D_/BN, M_/BM, 1), 256>>>(o, opw, aligned, opb, alphas, H, D_, 0, 0);

    // Qn/Kn/Vn = per-view aligned @ W^T
    gemm_nt<2><<<dim3(D_/BN, N_/BM, V_), 256>>>(aligned, WQ, Qn, nullptr, nullptr, nullptr, D_, N_*D_, D_*D_);
    gemm_nt<2><<<dim3(D_/BN, N_/BM, V_), 256>>>(aligned, WK, Kn, nullptr, nullptr, nullptr, D_, N_*D_, D_*D_);
    gemm_nt<2><<<dim3(D_/BN, N_/BM, V_), 256>>>(aligned, WV, Vn, nullptr, nullptr, nullptr, D_, N_*D_, D_*D_);

    // Vn column means
    meanv_part<<<dim3(V_, 8), 256>>>(Vn, meanP);
    meanv_reduce<<<V_, 256>>>(meanP, meanV);

    // sparse neighbor attention + final fusion
    nbr_final_kernel<<<dim3(N_, V_), 256>>>(Qn, Kn, Vn, meanV, idx, aligned, H, aal, beta, out);
}

// round 6
// speedup vs baseline: 1.1823x; 1.1818x over previous
#include <cuda_runtime.h>
#include <math.h>

#define V_ 4
#define N_ 1536
#define D_ 256
#define HEADS_ 4
#define DH_ 64
#define KTOP 32
#define M_ (V_*N_)    /* 6144 */
#define E3_ (3*D_)    /* 768  */

// ---------------- scratch ----------------
__device__ float g_qkv[M_*E3_];
__device__ float g_o[M_*D_];
__device__ float g_aligned[M_*D_];
__device__ float g_Qn[M_*D_];
__device__ float g_Kn[M_*D_];
__device__ float g_Vn[M_*D_];
__device__ float g_meanPart[V_*16*D_];
__device__ float g_meanV[V_*D_];
__device__ int   g_idx[V_*V_*N_*KTOP];

// ---------------- 64x64x16 double-buffered NT SGEMM ----------------
// C[m,e] = sum_k A[m,k] * B[e,k]   (K fixed = 256)
// MODE 0: O0 = acc + bias                 (E=768)
// MODE 1: O0 = alphas[v]*(acc+bias) + (1-alphas[v])*H   (E=256)
// MODE 3: fused QKV: e in [0,768) selects {WQ,WK,WV} -> {Qn,Kn,Vn}, per-view z
#define BM 64
#define BN 64
#define BK 16
#define TT (D_/BK)   /* 16 */

template<int MODE>
__global__ void __launch_bounds__(128) gemm64(
    const float* __restrict__ A, const float* __restrict__ B0,
    const float* __restrict__ B1, const float* __restrict__ B2,
    float* __restrict__ O0, float* __restrict__ O1, float* __restrict__ O2,
    const float* __restrict__ bias, const float* __restrict__ alphas,
    const float* __restrict__ Hin)
{
    __shared__ float As[2][BK][BM+4];
    __shared__ float Bs[2][BK][BN+4];

    const int tid = threadIdx.x;
    const int tx = tid & 15, ty = tid >> 4;
    const int mBase = blockIdx.y * BM;
    const int eBase = blockIdx.x * BN;
    const int z = blockIdx.z;

    const float* Ap = A;
    const float* Bp = B0;
    int eLoc = eBase;
    int seg = 0;
    if (MODE == 3) {
        Ap = A + (size_t)z * N_ * D_;
        seg = eBase >> 8;
        Bp = (seg == 0 ? B0 : (seg == 1 ? B1 : B2)) + (size_t)z * D_ * D_;
        eLoc = eBase & 255;
    }

    const int lr = tid >> 2;          // 0..31
    const int lc4 = tid & 3;          // 0..3

    float4 a4[2], b4[2];
    // ---- preload tile 0 ----
#pragma unroll
    for (int it = 0; it < 2; ++it) {
        int r = lr + it * 32;
        a4[it] = *reinterpret_cast<const float4*>(Ap + (size_t)(mBase + r) * D_ + lc4 * 4);
        b4[it] = *reinterpret_cast<const float4*>(Bp + (size_t)(eLoc  + r) * D_ + lc4 * 4);
    }
#pragma unroll
    for (int it = 0; it < 2; ++it) {
        int r = lr + it * 32;
        As[0][lc4*4+0][r] = a4[it].x; As[0][lc4*4+1][r] = a4[it].y;
        As[0][lc4*4+2][r] = a4[it].z; As[0][lc4*4+3][r] = a4[it].w;
        Bs[0][lc4*4+0][r] = b4[it].x; Bs[0][lc4*4+1][r] = b4[it].y;
        Bs[0][lc4*4+2][r] = b4[it].z; Bs[0][lc4*4+3][r] = b4[it].w;
    }
    __syncthreads();

    float acc[8][4];
#pragma unroll
    for (int i = 0; i < 8; ++i)
#pragma unroll
        for (int j = 0; j < 4; ++j) acc[i][j] = 0.f;

    int buf = 0;
    for (int t = 0; t < TT; ++t) {
        if (t + 1 < TT) {
            int kk = (t + 1) * BK;
#pragma unroll
            for (int it = 0; it < 2; ++it) {
                int r = lr + it * 32;
                a4[it] = *reinterpret_cast<const float4*>(Ap + (size_t)(mBase + r) * D_ + kk + lc4 * 4);
                b4[it] = *reinterpret_cast<const float4*>(Bp + (size_t)(eLoc  + r) * D_ + kk + lc4 * 4);
            }
        }
#pragma unroll
        for (int k = 0; k < BK; ++k) {
            float4 A0 = *reinterpret_cast<const float4*>(&As[buf][k][ty*8]);
            float4 A1 = *reinterpret_cast<const float4*>(&As[buf][k][ty*8+4]);
            float4 Bb = *reinterpret_cast<const float4*>(&Bs[buf][k][tx*4]);
            float a[8] = {A0.x, A0.y, A0.z, A0.w, A1.x, A1.y, A1.z, A1.w};
            float b[4] = {Bb.x, Bb.y, Bb.z, Bb.w};
#pragma unroll
            for (int i = 0; i < 8; ++i)
#pragma unroll
                for (int j = 0; j < 4; ++j)
                    acc[i][j] = fmaf(a[i], b[j], acc[i][j]);
        }
        if (t + 1 < TT) {
            int nb = buf ^ 1;
#pragma unroll
            for (int it = 0; it < 2; ++it) {
                int r = lr + it * 32;
                As[nb][lc4*4+0][r] = a4[it].x; As[nb][lc4*4+1][r] = a4[it].y;
                As[nb][lc4*4+2][r] = a4[it].z; As[nb][lc4*4+3][r] = a4[it].w;
                Bs[nb][lc4*4+0][r] = b4[it].x; Bs[nb][lc4*4+1][r] = b4[it].y;
                Bs[nb][lc4*4+2][r] = b4[it].z; Bs[nb][lc4*4+3][r] = b4[it].w;
            }
            __syncthreads();
            buf = nb;
        }
    }

    // ---- epilogue ----
#pragma unroll
    for (int i = 0; i < 8; ++i) {
        int row = mBase + ty * 8 + i;
#pragma unroll
        for (int j = 0; j < 4; ++j) {
            int col = eBase + tx * 4 + j;
            float val = acc[i][j];
            if (MODE == 0) {
                O0[(size_t)row * E3_ + col] = val + bias[col];
            } else if (MODE == 1) {
                int v = row / N_;
                float al = alphas[v];
                val = al * (val + bias[col]) + (1.f - al) * Hin[(size_t)row * D_ + col];
                O0[(size_t)row * D_ + col] = val;
            } else { // MODE 3
                int colLoc = col & 255;
                float* Op = (seg == 0) ? O0 : (seg == 1 ? O1 : O2);
                Op[((size_t)z * N_ + row) * D_ + colLoc] = val;
            }
        }
    }
}

// ---------------- per-(n,h) 4x4 view attention ----------------
__global__ void attn_kernel(const float* __restrict__ qkv, float* __restrict__ o)
{
    int gw = (blockIdx.x * blockDim.x + threadIdx.x) >> 5;
    int lane = threadIdx.x & 31;
    if (gw >= N_ * HEADS_) return;
    int n = gw >> 2;
    int h = gw & 3;

    float q[4][2], k[4][2], v[4][2];
#pragma unroll
    for (int s = 0; s < 4; ++s) {
        size_t base = ((size_t)s * N_ + n) * E3_ + h * DH_ + lane;
        q[s][0] = qkv[base];          q[s][1] = qkv[base + 32];
        k[s][0] = qkv[base + D_];     k[s][1] = qkv[base + D_ + 32];
        v[s][0] = qkv[base + 2*D_];   v[s][1] = qkv[base + 2*D_ + 32];
    }
    float att[4][4];
#pragma unroll
    for (int s = 0; s < 4; ++s)
#pragma unroll
        for (int t = 0; t < 4; ++t) {
            float p = q[s][0]*k[t][0] + q[s][1]*k[t][1];
#pragma unroll
            for (int off = 16; off; off >>= 1) p += __shfl_xor_sync(0xffffffffu, p, off);
            att[s][t] = p * 0.125f;
        }
#pragma unroll
    for (int s = 0; s < 4; ++s) {
        float mx = fmaxf(fmaxf(att[s][0], att[s][1]), fmaxf(att[s][2], att[s][3]));
        float e0 = expf(att[s][0] - mx), e1 = expf(att[s][1] - mx);
        float e2 = expf(att[s][2] - mx), e3 = expf(att[s][3] - mx);
        float inv = 1.f / (e0 + e1 + e2 + e3);
        float w0 = e0*inv, w1 = e1*inv, w2 = e2*inv, w3 = e3*inv;
        float o0 = w0*v[0][0] + w1*v[1][0] + w2*v[2][0] + w3*v[3][0];
        float o1 = w0*v[0][1] + w1*v[1][1] + w2*v[2][1] + w3*v[3][1];
        size_t ob = ((size_t)s * N_ + n) * D_ + h * DH_ + lane;
        o[ob] = o0; o[ob + 32] = o1;
    }
}

// ---------------- top-32: register-resident keys, 32 argmax passes ----------------
__global__ void __launch_bounds__(128) topk_kernel(const float* __restrict__ C, int* __restrict__ outIdx)
{
    int n = blockIdx.x;
    int pid = blockIdx.y;              // 0..11 off-diagonal pairs
    int p = pid / 3;
    int qo = pid % 3;
    int q = qo + (qo >= p ? 1 : 0);
    const float* row = C + (((size_t)p * V_ + q) * N_ + n) * (size_t)N_;

    __shared__ unsigned long long wbest[2][4];
    __shared__ int   selIdx[KTOP];
    __shared__ float selVal[KTOP];

    int tid = threadIdx.x, lane = tid & 31, warp = tid >> 5;

    // 12 keys per thread, in registers
    unsigned long long key[12];
#pragma unroll
    for (int s = 0; s < 3; ++s) {
        int li = tid + s * 128;                 // float4 index 0..383
        float4 t = *reinterpret_cast<const float4*>(row + (size_t)li * 4);
        float vv[4] = {t.x, t.y, t.z, t.w};
#pragma unroll
        for (int j = 0; j < 4; ++j) {
            unsigned u = __float_as_uint(vv[j]);
            u = (u & 0x80000000u) ? ~u : (u | 0x80000000u);
            unsigned i = (unsigned)(li * 4 + j);
            key[s*4+j] = ((unsigned long long)u << 32) | (0xFFFFFFFFu - i);
        }
    }

    for (int it = 0; it < KTOP; ++it) {
        unsigned long long m = key[0];
#pragma unroll
        for (int j = 1; j < 12; ++j) m = (key[j] > m) ? key[j] : m;
#pragma unroll
        for (int off = 16; off; off >>= 1) {
            unsigned long long o = __shfl_xor_sync(0xffffffffu, m, off);
            m = (o > m) ? o : m;
        }
        int pb = it & 1;
        if (lane == 0) wbest[pb][warp] = m;
        __syncthreads();
        unsigned long long w = wbest[pb][0];
#pragma unroll
        for (int w2 = 1; w2 < 4; ++w2) w = (wbest[pb][w2] > w) ? wbest[pb][w2] : w;
        // clear winner (unique key)
#pragma unroll
        for (int j = 0; j < 12; ++j) if (key[j] == w) key[j] = 0ull;
        if (tid == 0) {
            unsigned u = (unsigned)(w >> 32);
            unsigned orig = (u & 0x80000000u) ? (u & 0x7FFFFFFFu) : ~u;
            selVal[it] = __uint_as_float(orig);
            selIdx[it] = (int)(0xFFFFFFFFu - (unsigned)(w & 0xFFFFFFFFull));
        }
    }
    __syncthreads();

    if (tid < KTOP) {
        float rs = 0.f;
#pragma unroll
        for (int j = 0; j < KTOP; ++j) rs += selVal[j];
        rs += 1e-12f;
        bool m = (selVal[tid] / rs) > 0.f;
        outIdx[(((size_t)p * V_ + q) * N_ + n) * KTOP + tid] = m ? selIdx[tid] : -1;
    }
}

// ---------------- Vn column means ----------------
__global__ void meanv_part(const float* __restrict__ Vn, float* __restrict__ part)
{
    int v = blockIdx.x, s = blockIdx.y, d = threadIdx.x;
    int m0 = s * (N_ / 16);
    float acc = 0.f;
#pragma unroll 8
    for (int m = 0; m < N_ / 16; ++m)
        acc += Vn[((size_t)v * N_ + m0 + m) * D_ + d];
    part[((size_t)v * 16 + s) * D_ + d] = acc;
}

__global__ void meanv_reduce(const float* __restrict__ part, float* __restrict__ meanV)
{
    int v = blockIdx.x, d = threadIdx.x;
    float acc = 0.f;
#pragma unroll
    for (int s = 0; s < 16; ++s) acc += part[((size_t)v * 16 + s) * D_ + d];
    meanV[v * D_ + d] = acc * (1.0f / N_);
}

// ---------------- sparse neighbor attention + final fuse ----------------
__global__ void __launch_bounds__(256) nbr_final_kernel(
    const float* __restrict__ Qn, const float* __restrict__ Kn, const float* __restrict__ Vn,
    const float* __restrict__ meanV, const int* __restrict__ topIdx,
    const float* __restrict__ aligned, const float* __restrict__ Hin,
    const float* __restrict__ alpha_align, const float* __restrict__ beta,
    float* __restrict__ out)
{
    int n = blockIdx.x, p = blockIdx.y;
    int tid = threadIdx.x;
    int lane = tid & 31, warp = tid >> 5;

    __shared__ float qs[D_];
    __shared__ int   sidx[KTOP];
    __shared__ float sw[KTOP];
    __shared__ int   uniformFlag;

    qs[tid] = Qn[((size_t)p * N_ + n) * D_ + tid];
    float acc = meanV[p * D_ + tid];           // q == p: uniform softmax = mean of Vn[p]

    for (int qq = 0; qq < V_; ++qq) {
        if (qq == p) continue;
        __syncthreads();
        if (tid < KTOP) sidx[tid] = topIdx[(((size_t)p * V_ + qq) * N_ + n) * KTOP + tid];
        __syncthreads();

        // each warp computes 4 interleaved dot products (j = warp, warp+8, +16, +24)
        {
            int i0 = sidx[warp], i1 = sidx[warp+8], i2 = sidx[warp+16], i3 = sidx[warp+24];
            const float* r0 = Kn + ((size_t)qq * N_ + (i0 >= 0 ? i0 : 0)) * D_;
            const float* r1 = Kn + ((size_t)qq * N_ + (i1 >= 0 ? i1 : 0)) * D_;
            const float* r2 = Kn + ((size_t)qq * N_ + (i2 >= 0 ? i2 : 0)) * D_;
            const float* r3 = Kn + ((size_t)qq * N_ + (i3 >= 0 ? i3 : 0)) * D_;
            float s0 = 0.f, s1 = 0.f, s2 = 0.f, s3 = 0.f;
#pragma unroll
            for (int c = 0; c < 8; ++c) {
                float qv = qs[c * 32 + lane];
                s0 = fmaf(qv, r0[c * 32 + lane], s0);
                s1 = fmaf(qv, r1[c * 32 + lane], s1);
                s2 = fmaf(qv, r2[c * 32 + lane], s2);
                s3 = fmaf(qv, r3[c * 32 + lane], s3);
            }
#pragma unroll
            for (int off = 16; off; off >>= 1) {
                s0 += __shfl_xor_sync(0xffffffffu, s0, off);
                s1 += __shfl_xor_sync(0xffffffffu, s1, off);
                s2 += __shfl_xor_sync(0xffffffffu, s2, off);
                s3 += __shfl_xor_sync(0xffffffffu, s3, off);
            }
            if (lane == 0) {
                sw[warp]      = (i0 >= 0) ? s0 * 0.0625f : -3.4e38f;
                sw[warp + 8]  = (i1 >= 0) ? s1 * 0.0625f : -3.4e38f;
                sw[warp + 16] = (i2 >= 0) ? s2 * 0.0625f : -3.4e38f;
                sw[warp + 24] = (i3 >= 0) ? s3 * 0.0625f : -3.4e38f;
            }
        }
        __syncthreads();

        if (warp == 0) {
            int id = sidx[lane];
            float s = sw[lane];
            unsigned validMask = __ballot_sync(0xffffffffu, id >= 0);
            float mx = (id >= 0) ? s : -3.4e38f;
#pragma unroll
            for (int off = 16; off; off >>= 1) mx = fmaxf(mx, __shfl_xor_sync(0xffffffffu, mx, off));
            float e = (id >= 0) ? expf(s - mx) : 0.f;
            float sum = e;
#pragma unroll
            for (int off = 16; off; off >>= 1) sum += __shfl_xor_sync(0xffffffffu, sum, off);
            sw[lane] = (validMask == 0u) ? 0.f : e / sum;
            if (lane == 0) uniformFlag = (validMask == 0u);
        }
        __syncthreads();

        if (uniformFlag) {
            acc += meanV[qq * D_ + tid];
        } else {
            float a0 = 0.f, a1 = 0.f, a2 = 0.f, a3 = 0.f;
#pragma unroll
            for (int j = 0; j < KTOP; j += 4) {
                int i0 = sidx[j], i1 = sidx[j+1], i2 = sidx[j+2], i3 = sidx[j+3];
                if (i0 >= 0) a0 = fmaf(sw[j],   Vn[((size_t)qq * N_ + i0) * D_ + tid], a0);
                if (i1 >= 0) a1 = fmaf(sw[j+1], Vn[((size_t)qq * N_ + i1) * D_ + tid], a1);
                if (i2 >= 0) a2 = fmaf(sw[j+2], Vn[((size_t)qq * N_ + i2) * D_ + tid], a2);
                if (i3 >= 0) a3 = fmaf(sw[j+3], Vn[((size_t)qq * N_ + i3) * D_ + tid], a3);
            }
            acc += (a0 + a1) + (a2 + a3);
        }
    }

    float al = aligned[((size_t)p * N_ + n) * D_ + tid];
    float a  = 1.f / (1.f + expf(-alpha_align[0]));
    float f  = fmaxf(a * al + (1.f - a) * acc, 0.f);
    float b  = beta[0];
    out[((size_t)p * N_ + n) * D_ + tid] =
        b * Hin[((size_t)p * N_ + n) * D_ + tid] + (1.f - b) * f;
}

// ---------------- launch ----------------
extern "C" void kernel_launch(void* const* d_in, const int* in_sizes, int n_in,
                              void* d_out, int out_size)
{
    const float* H      = (const float*)d_in[0];
    const float* C      = (const float*)d_in[1];
    const float* WQ     = (const float*)d_in[2];
    const float* WK     = (const float*)d_in[3];
    const float* WV     = (const float*)d_in[4];
    const float* ipw    = (const float*)d_in[5];
    const float* ipb    = (const float*)d_in[6];
    const float* opw    = (const float*)d_in[7];
    const float* opb    = (const float*)d_in[8];
    const float* alphas = (const float*)d_in[9];
    const float* aal    = (const float*)d_in[10];
    const float* beta   = (const float*)d_in[11];
    float* out = (float*)d_out;

    float *qkv, *o, *aligned, *Qn, *Kn, *Vn, *meanP, *meanV;
    int* idx;
    cudaGetSymbolAddress((void**)&qkv,     g_qkv);
    cudaGetSymbolAddress((void**)&o,       g_o);
    cudaGetSymbolAddress((void**)&aligned, g_aligned);
    cudaGetSymbolAddress((void**)&Qn,      g_Qn);
    cudaGetSymbolAddress((void**)&Kn,      g_Kn);
    cudaGetSymbolAddress((void**)&Vn,      g_Vn);
    cudaGetSymbolAddress((void**)&meanP,   g_meanPart);
    cudaGetSymbolAddress((void**)&meanV,   g_meanV);
    cudaGetSymbolAddress((void**)&idx,     g_idx);

    // top-k depends only on C
    topk_kernel<<<dim3(N_, 12), 128>>>(C, idx);

    // qkv = H @ in_proj_w^T + b            grid 12 x 96
    gemm64<0><<<dim3(E3_/BN, M_/BM, 1), 128>>>(H, ipw, nullptr, nullptr,
                                               qkv, nullptr, nullptr, ipb, nullptr, nullptr);

    // per-(n,h) 4x4 view attention
    attn_kernel<<<(N_*HEADS_)/8, 256>>>(qkv, o);

    // aligned = alphas*(o @ out_proj^T + b) + (1-alphas)*H     grid 4 x 96
    gemm64<1><<<dim3(D_/BN, M_/BM, 1), 128>>>(o, opw, nullptr, nullptr,
                                              aligned, nullptr, nullptr, opb, alphas, H);

    // fused Qn/Kn/Vn = per-view aligned @ {WQ,WK,WV}^T          grid 12 x 24 x 4
    gemm64<3><<<dim3(E3_/BN, N_/BM, V_), 128>>>(aligned, WQ, WK, WV,
                                                Qn, Kn, Vn, nullptr, nullptr, nullptr);

    // Vn column means
    meanv_part<<<dim3(V_, 16), 256>>>(Vn, meanP);
    meanv_reduce<<<V_, 256>>>(meanP, meanV);

    // sparse neighbor attention + final fusion
    nbr_final_kernel<<<dim3(N_, V_), 256>>>(Qn, Kn, Vn, meanV, idx, aligned, H, aal, beta, out);
}

// round 8
// speedup vs baseline: 2.1400x; 1.8101x over previous
#include <cuda_runtime.h>
#include <math.h>

#define V_ 4
#define N_ 1536
#define D_ 256
#define HEADS_ 4
#define DH_ 64
#define KTOP 32
#define M_ (V_*N_)    /* 6144 */
#define E3_ (3*D_)    /* 768  */

// ---------------- scratch ----------------
__device__ float g_qkv[M_*E3_];
__device__ float g_o[M_*D_];
__device__ float g_aligned[M_*D_];
__device__ float g_Qn[M_*D_];
__device__ float g_Kn[M_*D_];
__device__ float g_Vn[M_*D_];
__device__ float g_meanPart[V_*16*D_];
__device__ float g_meanV[V_*D_];
__device__ int   g_idx[V_*V_*N_*KTOP];

// ---------------- 64x64x16 double-buffered NT SGEMM ----------------
// C[m,e] = sum_k A[m,k] * B[e,k]   (K fixed = 256)
// MODE 0: O0 = acc + bias                 (E=768)
// MODE 1: O0 = alphas[v]*(acc+bias) + (1-alphas[v])*H   (E=256)
// MODE 3: fused QKV: e in [0,768) selects {WQ,WK,WV} -> {Qn,Kn,Vn}, per-view z
#define BM 64
#define BN 64
#define BK 16
#define TT (D_/BK)   /* 16 */

template<int MODE>
__global__ void __launch_bounds__(128) gemm64(
    const float* __restrict__ A, const float* __restrict__ B0,
    const float* __restrict__ B1, const float* __restrict__ B2,
    float* __restrict__ O0, float* __restrict__ O1, float* __restrict__ O2,
    const float* __restrict__ bias, const float* __restrict__ alphas,
    const float* __restrict__ Hin)
{
    __shared__ float As[2][BK][BM+4];
    __shared__ float Bs[2][BK][BN+4];

    const int tid = threadIdx.x;
    const int tx = tid & 15, ty = tid >> 4;
    const int mBase = blockIdx.y * BM;
    const int eBase = blockIdx.x * BN;
    const int z = blockIdx.z;

    const float* Ap = A;
    const float* Bp = B0;
    int eLoc = eBase;
    int seg = 0;
    if (MODE == 3) {
        Ap = A + (size_t)z * N_ * D_;
        seg = eBase >> 8;
        Bp = (seg == 0 ? B0 : (seg == 1 ? B1 : B2)) + (size_t)z * D_ * D_;
        eLoc = eBase & 255;
    }

    const int lr = tid >> 2;          // 0..31
    const int lc4 = tid & 3;          // 0..3

    float4 a4[2], b4[2];
    // ---- preload tile 0 ----
#pragma unroll
    for (int it = 0; it < 2; ++it) {
        int r = lr + it * 32;
        a4[it] = *reinterpret_cast<const float4*>(Ap + (size_t)(mBase + r) * D_ + lc4 * 4);
        b4[it] = *reinterpret_cast<const float4*>(Bp + (size_t)(eLoc  + r) * D_ + lc4 * 4);
    }
#pragma unroll
    for (int it = 0; it < 2; ++it) {
        int r = lr + it * 32;
        As[0][lc4*4+0][r] = a4[it].x; As[0][lc4*4+1][r] = a4[it].y;
        As[0][lc4*4+2][r] = a4[it].z; As[0][lc4*4+3][r] = a4[it].w;
        Bs[0][lc4*4+0][r] = b4[it].x; Bs[0][lc4*4+1][r] = b4[it].y;
        Bs[0][lc4*4+2][r] = b4[it].z; Bs[0][lc4*4+3][r] = b4[it].w;
    }
    __syncthreads();

    float acc[8][4];
#pragma unroll
    for (int i = 0; i < 8; ++i)
#pragma unroll
        for (int j = 0; j < 4; ++j) acc[i][j] = 0.f;

    int buf = 0;
    for (int t = 0; t < TT; ++t) {
        if (t + 1 < TT) {
            int kk = (t + 1) * BK;
#pragma unroll
            for (int it = 0; it < 2; ++it) {
                int r = lr + it * 32;
                a4[it] = *reinterpret_cast<const float4*>(Ap + (size_t)(mBase + r) * D_ + kk + lc4 * 4);
                b4[it] = *reinterpret_cast<const float4*>(Bp + (size_t)(eLoc  + r) * D_ + kk + lc4 * 4);
            }
        }
#pragma unroll
        for (int k = 0; k < BK; ++k) {
            float4 A0 = *reinterpret_cast<const float4*>(&As[buf][k][ty*8]);
            float4 A1 = *reinterpret_cast<const float4*>(&As[buf][k][ty*8+4]);
            float4 Bb = *reinterpret_cast<const float4*>(&Bs[buf][k][tx*4]);
            float a[8] = {A0.x, A0.y, A0.z, A0.w, A1.x, A1.y, A1.z, A1.w};
            float b[4] = {Bb.x, Bb.y, Bb.z, Bb.w};
#pragma unroll
            for (int i = 0; i < 8; ++i)
#pragma unroll
                for (int j = 0; j < 4; ++j)
                    acc[i][j] = fmaf(a[i], b[j], acc[i][j]);
        }
        if (t + 1 < TT) {
            int nb = buf ^ 1;
#pragma unroll
            for (int it = 0; it < 2; ++it) {
                int r = lr + it * 32;
                As[nb][lc4*4+0][r] = a4[it].x; As[nb][lc4*4+1][r] = a4[it].y;
                As[nb][lc4*4+2][r] = a4[it].z; As[nb][lc4*4+3][r] = a4[it].w;
                Bs[nb][lc4*4+0][r] = b4[it].x; Bs[nb][lc4*4+1][r] = b4[it].y;
                Bs[nb][lc4*4+2][r] = b4[it].z; Bs[nb][lc4*4+3][r] = b4[it].w;
            }
            __syncthreads();
            buf = nb;
        }
    }

    // ---- epilogue ----
#pragma unroll
    for (int i = 0; i < 8; ++i) {
        int row = mBase + ty * 8 + i;
#pragma unroll
        for (int j = 0; j < 4; ++j) {
            int col = eBase + tx * 4 + j;
            float val = acc[i][j];
            if (MODE == 0) {
                O0[(size_t)row * E3_ + col] = val + bias[col];
            } else if (MODE == 1) {
                int v = row / N_;
                float al = alphas[v];
                val = al * (val + bias[col]) + (1.f - al) * Hin[(size_t)row * D_ + col];
                O0[(size_t)row * D_ + col] = val;
            } else { // MODE 3
                int colLoc = col & 255;
                float* Op = (seg == 0) ? O0 : (seg == 1 ? O1 : O2);
                Op[((size_t)z * N_ + row) * D_ + colLoc] = val;
            }
        }
    }
}

// ---------------- per-(n,h) 4x4 view attention ----------------
__global__ void attn_kernel(const float* __restrict__ qkv, float* __restrict__ o)
{
    int gw = (blockIdx.x * blockDim.x + threadIdx.x) >> 5;
    int lane = threadIdx.x & 31;
    if (gw >= N_ * HEADS_) return;
    int n = gw >> 2;
    int h = gw & 3;

    float q[4][2], k[4][2], v[4][2];
#pragma unroll
    for (int s = 0; s < 4; ++s) {
        size_t base = ((size_t)s * N_ + n) * E3_ + h * DH_ + lane;
        q[s][0] = qkv[base];          q[s][1] = qkv[base + 32];
        k[s][0] = qkv[base + D_];     k[s][1] = qkv[base + D_ + 32];
        v[s][0] = qkv[base + 2*D_];   v[s][1] = qkv[base + 2*D_ + 32];
    }
    float att[4][4];
#pragma unroll
    for (int s = 0; s < 4; ++s)
#pragma unroll
        for (int t = 0; t < 4; ++t) {
            float p = q[s][0]*k[t][0] + q[s][1]*k[t][1];
#pragma unroll
            for (int off = 16; off; off >>= 1) p += __shfl_xor_sync(0xffffffffu, p, off);
            att[s][t] = p * 0.125f;
        }
#pragma unroll
    for (int s = 0; s < 4; ++s) {
        float mx = fmaxf(fmaxf(att[s][0], att[s][1]), fmaxf(att[s][2], att[s][3]));
        float e0 = expf(att[s][0] - mx), e1 = expf(att[s][1] - mx);
        float e2 = expf(att[s][2] - mx), e3 = expf(att[s][3] - mx);
        float inv = 1.f / (e0 + e1 + e2 + e3);
        float w0 = e0*inv, w1 = e1*inv, w2 = e2*inv, w3 = e3*inv;
        float o0 = w0*v[0][0] + w1*v[1][0] + w2*v[2][0] + w3*v[3][0];
        float o1 = w0*v[0][1] + w1*v[1][1] + w2*v[2][1] + w3*v[3][1];
        size_t ob = ((size_t)s * N_ + n) * D_ + h * DH_ + lane;
        o[ob] = o0; o[ob + 32] = o1;
    }
}

// ---------------- top-32: u32 keys, incremental lane max, atomicMin tie-break ----------------
// Exact jax.lax.top_k semantics: descending values, ties broken by smallest index
// (duplicate values are extracted in ascending index order across passes).
__global__ void __launch_bounds__(128) topk_kernel(const float* __restrict__ C, int* __restrict__ outIdx)
{
    int n = blockIdx.x;
    int pid = blockIdx.y;              // 0..11 off-diagonal pairs
    int p = pid / 3;
    int qo = pid % 3;
    int q = qo + (qo >= p ? 1 : 0);
    const float* row = C + (((size_t)p * V_ + q) * N_ + n) * (size_t)N_;

    __shared__ unsigned wbest[4];
    __shared__ int      gmin[KTOP];
    __shared__ unsigned selKey[KTOP];
    __shared__ int      selIdx[KTOP];

    int tid = threadIdx.x, lane = tid & 31, warp = tid >> 5;

    // 12 orderable u32 keys per thread, in registers.
    // element global index for key[s*4+j] is (tid + s*128)*4 + j
    unsigned key[12];
#pragma unroll
    for (int s = 0; s < 3; ++s) {
        int li = tid + s * 128;
        float4 t = *reinterpret_cast<const float4*>(row + (size_t)li * 4);
        float vv[4] = {t.x, t.y, t.z, t.w};
#pragma unroll
        for (int j = 0; j < 4; ++j) {
            unsigned u = __float_as_uint(vv[j]);
            key[s*4+j] = (u & 0x80000000u) ? ~u : (u | 0x80000000u);
        }
    }
    if (tid < KTOP) gmin[tid] = 0x7FFFFFFF;

    unsigned tmax = key[0];
#pragma unroll
    for (int j = 1; j < 12; ++j) tmax = max(tmax, key[j]);
    __syncthreads();

    for (int it = 0; it < KTOP; ++it) {
        // warp max of lane maxes (u32, VIMNMX)
        unsigned m = tmax;
#pragma unroll
        for (int off = 16; off; off >>= 1) {
            unsigned o = __shfl_xor_sync(0xffffffffu, m, off);
            m = max(m, o);
        }
        if (lane == 0) wbest[warp] = m;
        __syncthreads();                                   // S1
        unsigned bm = max(max(wbest[0], wbest[1]), max(wbest[2], wbest[3]));

        // rare path: candidate threads locate smallest global element index with key==bm
        if (tmax == bm) {
            int bj = 0x7FFFFFFF;
#pragma unroll
            for (int s = 0; s < 3; ++s)
#pragma unroll
                for (int j = 0; j < 4; ++j) {
                    if (key[s*4+j] == bm) {
                        int gi = (tid + s * 128) * 4 + j;
                        bj = min(bj, gi);
                    }
                }
            atomicMin(&gmin[it], bj);
        }
        __syncthreads();                                   // S2

        int wg = gmin[it];
        // owner clears the extracted element and recomputes its lane max
        int ot = (wg >> 2) & 127;
        if (tid == ot) {
            int os = wg >> 9;
            int oj = wg & 3;
            key[os*4 + oj] = 0u;                           // sentinel: below any real key
            unsigned t2 = key[0];
#pragma unroll
            for (int j = 1; j < 12; ++j) t2 = max(t2, key[j]);
            tmax = t2;
        }
        if (tid == 0) { selKey[it] = bm; selIdx[it] = wg; }
        // no extra sync needed: wbest reads for this pass all happened before S2,
        // tmax update precedes the owner's next shfl in program order.
    }
    __syncthreads();

    if (tid < KTOP) {
        float rs = 0.f;
#pragma unroll
        for (int j = 0; j < KTOP; ++j) {
            unsigned ku = selKey[j];
            unsigned orig = (ku & 0x80000000u) ? (ku & 0x7FFFFFFFu) : ~ku;
            rs += __uint_as_float(orig);
        }
        rs += 1e-12f;
        unsigned ku = selKey[tid];
        unsigned orig = (ku & 0x80000000u) ? (ku & 0x7FFFFFFFu) : ~ku;
        float v = __uint_as_float(orig);
        bool msk = (v / rs) > 0.f;
        outIdx[(((size_t)p * V_ + q) * N_ + n) * KTOP + tid] = msk ? selIdx[tid] : -1;
    }
}

// ---------------- Vn column means ----------------
__global__ void meanv_part(const float* __restrict__ Vn, float* __restrict__ part)
{
    int v = blockIdx.x, s = blockIdx.y, d = threadIdx.x;
    int m0 = s * (N_ / 16);
    float acc = 0.f;
#pragma unroll 8
    for (int m = 0; m < N_ / 16; ++m)
        acc += Vn[((size_t)v * N_ + m0 + m) * D_ + d];
    part[((size_t)v * 16 + s) * D_ + d] = acc;
}

__global__ void meanv_reduce(const float* __restrict__ part, float* __restrict__ meanV)
{
    int v = blockIdx.x, d = threadIdx.x;
    float acc = 0.f;
#pragma unroll
    for (int s = 0; s < 16; ++s) acc += part[((size_t)v * 16 + s) * D_ + d];
    meanV[v * D_ + d] = acc * (1.0f / N_);
}

// ---------------- sparse neighbor attention + final fuse ----------------
__global__ void __launch_bounds__(256) nbr_final_kernel(
    const float* __restrict__ Qn, const float* __restrict__ Kn, const float* __restrict__ Vn,
    const float* __restrict__ meanV, const int* __restrict__ topIdx,
    const float* __restrict__ aligned, const float* __restrict__ Hin,
    const float* __restrict__ alpha_align, const float* __restrict__ beta,
    float* __restrict__ out)
{
    int n = blockIdx.x, p = blockIdx.y;
    int tid = threadIdx.x;
    int lane = tid & 31, warp = tid >> 5;

    __shared__ float qs[D_];
    __shared__ int   sidx[KTOP];
    __shared__ float sw[KTOP];
    __shared__ int   uniformFlag;

    qs[tid] = Qn[((size_t)p * N_ + n) * D_ + tid];
    float acc = meanV[p * D_ + tid];           // q == p: uniform softmax = mean of Vn[p]

    for (int qq = 0; qq < V_; ++qq) {
        if (qq == p) continue;
        __syncthreads();
        if (tid < KTOP) sidx[tid] = topIdx[(((size_t)p * V_ + qq) * N_ + n) * KTOP + tid];
        __syncthreads();

        // each warp computes 4 interleaved dot products (j = warp, warp+8, +16, +24)
        {
            int i0 = sidx[warp], i1 = sidx[warp+8], i2 = sidx[warp+16], i3 = sidx[warp+24];
            const float* r0 = Kn + ((size_t)qq * N_ + (i0 >= 0 ? i0 : 0)) * D_;
            const float* r1 = Kn + ((size_t)qq * N_ + (i1 >= 0 ? i1 : 0)) * D_;
            const float* r2 = Kn + ((size_t)qq * N_ + (i2 >= 0 ? i2 : 0)) * D_;
            const float* r3 = Kn + ((size_t)qq * N_ + (i3 >= 0 ? i3 : 0)) * D_;
            float s0 = 0.f, s1 = 0.f, s2 = 0.f, s3 = 0.f;
#pragma unroll
            for (int c = 0; c < 8; ++c) {
                float qv = qs[c * 32 + lane];
                s0 = fmaf(qv, r0[c * 32 + lane], s0);
                s1 = fmaf(qv, r1[c * 32 + lane], s1);
                s2 = fmaf(qv, r2[c * 32 + lane], s2);
                s3 = fmaf(qv, r3[c * 32 + lane], s3);
            }
#pragma unroll
            for (int off = 16; off; off >>= 1) {
                s0 += __shfl_xor_sync(0xffffffffu, s0, off);
                s1 += __shfl_xor_sync(0xffffffffu, s1, off);
                s2 += __shfl_xor_sync(0xffffffffu, s2, off);
                s3 += __shfl_xor_sync(0xffffffffu, s3, off);
            }
            if (lane == 0) {
                sw[warp]      = (i0 >= 0) ? s0 * 0.0625f : -3.4e38f;
                sw[warp + 8]  = (i1 >= 0) ? s1 * 0.0625f : -3.4e38f;
                sw[warp + 16] = (i2 >= 0) ? s2 * 0.0625f : -3.4e38f;
                sw[warp + 24] = (i3 >= 0) ? s3 * 0.0625f : -3.4e38f;
            }
        }
        __syncthreads();

        if (warp == 0) {
            int id = sidx[lane];
            float s = sw[lane];
            unsigned validMask = __ballot_sync(0xffffffffu, id >= 0);
            float mx = (id >= 0) ? s : -3.4e38f;
#pragma unroll
            for (int off = 16; off; off >>= 1) mx = fmaxf(mx, __shfl_xor_sync(0xffffffffu, mx, off));
            float e = (id >= 0) ? expf(s - mx) : 0.f;
            float sum = e;
#pragma unroll
            for (int off = 16; off; off >>= 1) sum += __shfl_xor_sync(0xffffffffu, sum, off);
            sw[lane] = (validMask == 0u) ? 0.f : e / sum;
            if (lane == 0) uniformFlag = (validMask == 0u);
        }
        __syncthreads();

        if (uniformFlag) {
            acc += meanV[qq * D_ + tid];
        } else {
            float a0 = 0.f, a1 = 0.f, a2 = 0.f, a3 = 0.f;
#pragma unroll
            for (int j = 0; j < KTOP; j += 4) {
                int i0 = sidx[j], i1 = sidx[j+1], i2 = sidx[j+2], i3 = sidx[j+3];
                if (i0 >= 0) a0 = fmaf(sw[j],   Vn[((size_t)qq * N_ + i0) * D_ + tid], a0);
                if (i1 >= 0) a1 = fmaf(sw[j+1], Vn[((size_t)qq * N_ + i1) * D_ + tid], a1);
                if (i2 >= 0) a2 = fmaf(sw[j+2], Vn[((size_t)qq * N_ + i2) * D_ + tid], a2);
                if (i3 >= 0) a3 = fmaf(sw[j+3], Vn[((size_t)qq * N_ + i3) * D_ + tid], a3);
            }
            acc += (a0 + a1) + (a2 + a3);
        }
    }

    float al = aligned[((size_t)p * N_ + n) * D_ + tid];
    float a  = 1.f / (1.f + expf(-alpha_align[0]));
    float f  = fmaxf(a * al + (1.f - a) * acc, 0.f);
    float b  = beta[0];
    out[((size_t)p * N_ + n) * D_ + tid] =
        b * Hin[((size_t)p * N_ + n) * D_ + tid] + (1.f - b) * f;
}

// ---------------- launch ----------------
extern "C" void kernel_launch(void* const* d_in, const int* in_sizes, int n_in,
                              void* d_out, int out_size)
{
    const float* H      = (const float*)d_in[0];
    const float* C      = (const float*)d_in[1];
    const float* WQ     = (const float*)d_in[2];
    const float* WK     = (const float*)d_in[3];
    const float* WV     = (const float*)d_in[4];
    const float* ipw    = (const float*)d_in[5];
    const float* ipb    = (const float*)d_in[6];
    const float* opw    = (const float*)d_in[7];
    const float* opb    = (const float*)d_in[8];
    const float* alphas = (const float*)d_in[9];
    const float* aal    = (const float*)d_in[10];
    const float* beta   = (const float*)d_in[11];
    float* out = (float*)d_out;

    float *qkv, *o, *aligned, *Qn, *Kn, *Vn, *meanP, *meanV;
    int* idx;
    cudaGetSymbolAddress((void**)&qkv,     g_qkv);
    cudaGetSymbolAddress((void**)&o,       g_o);
    cudaGetSymbolAddress((void**)&aligned, g_aligned);
    cudaGetSymbolAddress((void**)&Qn,      g_Qn);
    cudaGetSymbolAddress((void**)&Kn,      g_Kn);
    cudaGetSymbolAddress((void**)&Vn,      g_Vn);
    cudaGetSymbolAddress((void**)&meanP,   g_meanPart);
    cudaGetSymbolAddress((void**)&meanV,   g_meanV);
    cudaGetSymbolAddress((void**)&idx,     g_idx);

    // top-k depends only on C
    topk_kernel<<<dim3(N_, 12), 128>>>(C, idx);

    // qkv = H @ in_proj_w^T + b            grid 12 x 96
    gemm64<0><<<dim3(E3_/BN, M_/BM, 1), 128>>>(H, ipw, nullptr, nullptr,
                                               qkv, nullptr, nullptr, ipb, nullptr, nullptr);

    // per-(n,h) 4x4 view attention
    attn_kernel<<<(N_*HEADS_)/8, 256>>>(qkv, o);

    // aligned = alphas*(o @ out_proj^T + b) + (1-alphas)*H     grid 4 x 96
    gemm64<1><<<dim3(D_/BN, M_/BM, 1), 128>>>(o, opw, nullptr, nullptr,
                                              aligned, nullptr, nullptr, opb, alphas, H);

    // fused Qn/Kn/Vn = per-view aligned @ {WQ,WK,WV}^T          grid 12 x 24 x 4
    gemm64<3><<<dim3(E3_/BN, N_/BM, V_), 128>>>(aligned, WQ, WK, WV,
                                                Qn, Kn, Vn, nullptr, nullptr, nullptr);

    // Vn column means
    meanv_part<<<dim3(V_, 16), 256>>>(Vn, meanP);
    meanv_reduce<<<V_, 256>>>(meanP, meanV);

    // sparse neighbor attention + final fusion
    nbr_final_kernel<<<dim3(N_, V_), 256>>>(Qn, Kn, Vn, meanV, idx, aligned, H, aal, beta, out);
}

// round 9
// speedup vs baseline: 2.2574x; 1.0549x over previous
#include <cuda_runtime.h>
#include <math.h>

#define V_ 4
#define N_ 1536
#define D_ 256
#define HEADS_ 4
#define DH_ 64
#define KTOP 32
#define M_ (V_*N_)    /* 6144 */
#define E3_ (3*D_)    /* 768  */

// ---------------- scratch ----------------
__device__ float g_qkv[M_*E3_];
__device__ float g_o[M_*D_];
__device__ float g_aligned[M_*D_];
__device__ float g_Qn[M_*D_];
__device__ float g_Kn[M_*D_];
__device__ float g_Vn[M_*D_];
__device__ float g_meanPart[V_*16*D_];
__device__ float g_meanV[V_*D_];
__device__ int   g_idx[V_*V_*N_*KTOP];

// ---------------- 64x64x16 double-buffered NT SGEMM ----------------
#define BM 64
#define BN 64
#define BK 16
#define TT (D_/BK)   /* 16 */

template<int MODE>
__global__ void __launch_bounds__(128) gemm64(
    const float* __restrict__ A, const float* __restrict__ B0,
    const float* __restrict__ B1, const float* __restrict__ B2,
    float* __restrict__ O0, float* __restrict__ O1, float* __restrict__ O2,
    const float* __restrict__ bias, const float* __restrict__ alphas,
    const float* __restrict__ Hin)
{
    __shared__ float As[2][BK][BM+4];
    __shared__ float Bs[2][BK][BN+4];

    const int tid = threadIdx.x;
    const int tx = tid & 15, ty = tid >> 4;
    const int mBase = blockIdx.y * BM;
    const int eBase = blockIdx.x * BN;
    const int z = blockIdx.z;

    const float* Ap = A;
    const float* Bp = B0;
    int eLoc = eBase;
    int seg = 0;
    if (MODE == 3) {
        Ap = A + (size_t)z * N_ * D_;
        seg = eBase >> 8;
        Bp = (seg == 0 ? B0 : (seg == 1 ? B1 : B2)) + (size_t)z * D_ * D_;
        eLoc = eBase & 255;
    }

    const int lr = tid >> 2;          // 0..31
    const int lc4 = tid & 3;          // 0..3

    float4 a4[2], b4[2];
#pragma unroll
    for (int it = 0; it < 2; ++it) {
        int r = lr + it * 32;
        a4[it] = *reinterpret_cast<const float4*>(Ap + (size_t)(mBase + r) * D_ + lc4 * 4);
        b4[it] = *reinterpret_cast<const float4*>(Bp + (size_t)(eLoc  + r) * D_ + lc4 * 4);
    }
#pragma unroll
    for (int it = 0; it < 2; ++it) {
        int r = lr + it * 32;
        As[0][lc4*4+0][r] = a4[it].x; As[0][lc4*4+1][r] = a4[it].y;
        As[0][lc4*4+2][r] = a4[it].z; As[0][lc4*4+3][r] = a4[it].w;
        Bs[0][lc4*4+0][r] = b4[it].x; Bs[0][lc4*4+1][r] = b4[it].y;
        Bs[0][lc4*4+2][r] = b4[it].z; Bs[0][lc4*4+3][r] = b4[it].w;
    }
    __syncthreads();

    float acc[8][4];
#pragma unroll
    for (int i = 0; i < 8; ++i)
#pragma unroll
        for (int j = 0; j < 4; ++j) acc[i][j] = 0.f;

    int buf = 0;
    for (int t = 0; t < TT; ++t) {
        if (t + 1 < TT) {
            int kk = (t + 1) * BK;
#pragma unroll
            for (int it = 0; it < 2; ++it) {
                int r = lr + it * 32;
                a4[it] = *reinterpret_cast<const float4*>(Ap + (size_t)(mBase + r) * D_ + kk + lc4 * 4);
                b4[it] = *reinterpret_cast<const float4*>(Bp + (size_t)(eLoc  + r) * D_ + kk + lc4 * 4);
            }
        }
#pragma unroll
        for (int k = 0; k < BK; ++k) {
            float4 A0 = *reinterpret_cast<const float4*>(&As[buf][k][ty*8]);
            float4 A1 = *reinterpret_cast<const float4*>(&As[buf][k][ty*8+4]);
            float4 Bb = *reinterpret_cast<const float4*>(&Bs[buf][k][tx*4]);
            float a[8] = {A0.x, A0.y, A0.z, A0.w, A1.x, A1.y, A1.z, A1.w};
            float b[4] = {Bb.x, Bb.y, Bb.z, Bb.w};
#pragma unroll
            for (int i = 0; i < 8; ++i)
#pragma unroll
                for (int j = 0; j < 4; ++j)
                    acc[i][j] = fmaf(a[i], b[j], acc[i][j]);
        }
        if (t + 1 < TT) {
            int nb = buf ^ 1;
#pragma unroll
            for (int it = 0; it < 2; ++it) {
                int r = lr + it * 32;
                As[nb][lc4*4+0][r] = a4[it].x; As[nb][lc4*4+1][r] = a4[it].y;
                As[nb][lc4*4+2][r] = a4[it].z; As[nb][lc4*4+3][r] = a4[it].w;
                Bs[nb][lc4*4+0][r] = b4[it].x; Bs[nb][lc4*4+1][r] = b4[it].y;
                Bs[nb][lc4*4+2][r] = b4[it].z; Bs[nb][lc4*4+3][r] = b4[it].w;
            }
            __syncthreads();
            buf = nb;
        }
    }

#pragma unroll
    for (int i = 0; i < 8; ++i) {
        int row = mBase + ty * 8 + i;
#pragma unroll
        for (int j = 0; j < 4; ++j) {
            int col = eBase + tx * 4 + j;
            float val = acc[i][j];
            if (MODE == 0) {
                O0[(size_t)row * E3_ + col] = val + bias[col];
            } else if (MODE == 1) {
                int v = row / N_;
                float al = alphas[v];
                val = al * (val + bias[col]) + (1.f - al) * Hin[(size_t)row * D_ + col];
                O0[(size_t)row * D_ + col] = val;
            } else { // MODE 3
                int colLoc = col & 255;
                float* Op = (seg == 0) ? O0 : (seg == 1 ? O1 : O2);
                Op[((size_t)z * N_ + row) * D_ + colLoc] = val;
            }
        }
    }
}

// ---------------- per-(n,h) 4x4 view attention ----------------
__global__ void attn_kernel(const float* __restrict__ qkv, float* __restrict__ o)
{
    int gw = (blockIdx.x * blockDim.x + threadIdx.x) >> 5;
    int lane = threadIdx.x & 31;
    if (gw >= N_ * HEADS_) return;
    int n = gw >> 2;
    int h = gw & 3;

    float q[4][2], k[4][2], v[4][2];
#pragma unroll
    for (int s = 0; s < 4; ++s) {
        size_t base = ((size_t)s * N_ + n) * E3_ + h * DH_ + lane;
        q[s][0] = qkv[base];          q[s][1] = qkv[base + 32];
        k[s][0] = qkv[base + D_];     k[s][1] = qkv[base + D_ + 32];
        v[s][0] = qkv[base + 2*D_];   v[s][1] = qkv[base + 2*D_ + 32];
    }
    float att[4][4];
#pragma unroll
    for (int s = 0; s < 4; ++s)
#pragma unroll
        for (int t = 0; t < 4; ++t) {
            float p = q[s][0]*k[t][0] + q[s][1]*k[t][1];
#pragma unroll
            for (int off = 16; off; off >>= 1) p += __shfl_xor_sync(0xffffffffu, p, off);
            att[s][t] = p * 0.125f;
        }
#pragma unroll
    for (int s = 0; s < 4; ++s) {
        float mx = fmaxf(fmaxf(att[s][0], att[s][1]), fmaxf(att[s][2], att[s][3]));
        float e0 = expf(att[s][0] - mx), e1 = expf(att[s][1] - mx);
        float e2 = expf(att[s][2] - mx), e3 = expf(att[s][3] - mx);
        float inv = 1.f / (e0 + e1 + e2 + e3);
        float w0 = e0*inv, w1 = e1*inv, w2 = e2*inv, w3 = e3*inv;
        float o0 = w0*v[0][0] + w1*v[1][0] + w2*v[2][0] + w3*v[3][0];
        float o1 = w0*v[0][1] + w1*v[1][1] + w2*v[2][1] + w3*v[3][1];
        size_t ob = ((size_t)s * N_ + n) * D_ + h * DH_ + lane;
        o[ob] = o0; o[ob + 32] = o1;
    }
}

// ---------------- top-32 via radix select (12-bit histogram + exact boundary) ----------------
// Selected SET matches jax.lax.top_k exactly (value desc, smallest-index tie-break).
// Output slot order is arbitrary: downstream consumption is order-invariant.
__global__ void __launch_bounds__(128) topk_kernel(const float* __restrict__ C, int* __restrict__ outIdx)
{
    int n = blockIdx.x;
    int pid = blockIdx.y;              // 0..11 off-diagonal pairs
    int p = pid / 3;
    int qo = pid % 3;
    int q = qo + (qo >= p ? 1 : 0);
    const float* row = C + (((size_t)p * V_ + q) * N_ + n) * (size_t)N_;

    __shared__ int      hist[4096];
    __shared__ unsigned bk[N_];
    __shared__ int      bi[N_];
    __shared__ int      gsum[128];
    __shared__ int      tcnt[128];
    __shared__ int      selIdx[KTOP];
    __shared__ float    selVal[KTOP];
    __shared__ int      thrInfo[3];    // b, c0, m
    __shared__ int      bcnt;

    int tid = threadIdx.x, lane = tid & 31, warp = tid >> 5;

    // issue global loads early
    float4 t0 = *reinterpret_cast<const float4*>(row + (size_t)(tid)       * 4);
    float4 t1 = *reinterpret_cast<const float4*>(row + (size_t)(tid + 128) * 4);
    float4 t2 = *reinterpret_cast<const float4*>(row + (size_t)(tid + 256) * 4);

    // zero histogram
#pragma unroll
    for (int i = 0; i < 32; ++i) hist[tid + i * 128] = 0;
    if (tid == 0) bcnt = 0;
    __syncthreads();

    // orderable u32 keys, registers
    unsigned key[12];
    {
        float vv[12] = {t0.x, t0.y, t0.z, t0.w, t1.x, t1.y, t1.z, t1.w, t2.x, t2.y, t2.z, t2.w};
#pragma unroll
        for (int j = 0; j < 12; ++j) {
            unsigned u = __float_as_uint(vv[j]);
            key[j] = (u & 0x80000000u) ? ~u : (u | 0x80000000u);
        }
    }
    // element global index for key[j]: j<4 -> tid*4+j ; j<8 -> (tid+128)*4+(j-4) ; else (tid+256)*4+(j-8)
#pragma unroll
    for (int j = 0; j < 12; ++j) {
        atomicAdd(&hist[key[j] >> 20], 1);
    }
    __syncthreads();

    // group sums: group g covers bins [4095-32g-31, 4095-32g] (descending)
    {
        int g = tid;
        int hiBin = 4095 - 32 * g;
        int s = 0;
#pragma unroll
        for (int i = 0; i < 32; ++i) {
            int off = (i + g) & 31;          // rotate start to avoid bank conflicts
            s += hist[hiBin - off];
        }
        gsum[g] = s;
    }
    __syncthreads();

    // warp 0: find threshold bin b, count-above c0, needed-from-bin m
    if (warp == 0) {
        int a[4];
#pragma unroll
        for (int j = 0; j < 4; ++j) a[j] = gsum[lane * 4 + j];
        int psum = a[0] + a[1] + a[2] + a[3];
        int sc = psum;
#pragma unroll
        for (int off = 1; off < 32; off <<= 1) {
            int t = __shfl_up_sync(0xffffffffu, sc, off);
            if (lane >= off) sc += t;
        }
        int excl = sc - psum;
        unsigned bal = __ballot_sync(0xffffffffu, excl + psum >= KTOP);
        int L = __ffs(bal) - 1;
        if (lane == L) {
            int running = excl;
            int gg = 0;
#pragma unroll
            for (; gg < 4; ++gg) {
                if (running + a[gg] >= KTOP) break;
                running += a[gg];
            }
            int G = lane * 4 + gg;
            int hiBin = 4095 - 32 * G;
            int b = hiBin - 31;
            for (int i = 0; i < 32; ++i) {
                int bin = hiBin - i;
                int c = hist[bin];
                if (running + c >= KTOP) { b = bin; break; }
                running += c;
            }
            thrInfo[0] = b; thrInfo[1] = running; thrInfo[2] = KTOP - running;
        }
    }
    __syncthreads();

    const int b = thrInfo[0];

    // classify: sure-selected (bin > b) counted; boundary (bin == b) pushed
    int cnt = 0;
#pragma unroll
    for (int j = 0; j < 12; ++j) {
        unsigned bin = key[j] >> 20;
        if ((int)bin > b) cnt++;
        else if ((int)bin == b) {
            int gi = (j < 4) ? (tid * 4 + j) : ((j < 8) ? ((tid + 128) * 4 + j - 4) : ((tid + 256) * 4 + j - 8));
            int pos = atomicAdd(&bcnt, 1);
            bk[pos] = key[j];
            bi[pos] = gi;
        }
    }
    tcnt[tid] = cnt;
    __syncthreads();

    if (tid == 0) {                         // deterministic serial exclusive prefix
        int r = 0;
        for (int t = 0; t < 128; ++t) { int c = tcnt[t]; tcnt[t] = r; r += c; }
    }
    __syncthreads();

    {
        int w = tcnt[tid];
#pragma unroll
        for (int j = 0; j < 12; ++j) {
            if ((int)(key[j] >> 20) > b) {
                int gi = (j < 4) ? (tid * 4 + j) : ((j < 8) ? ((tid + 128) * 4 + j - 4) : ((tid + 256) * 4 + j - 8));
                unsigned ku = key[j];
                unsigned orig = (ku & 0x80000000u) ? (ku & 0x7FFFFFFFu) : ~ku;
                selIdx[w] = gi;
                selVal[w] = __uint_as_float(orig);
                w++;
            }
        }
    }
    __syncthreads();

    // warp 0: extract m winners from the boundary bin (value desc, smallest index first)
    if (warp == 0) {
        int c0 = thrInfo[1], m = thrInfo[2];
        int cntB = bcnt;
        for (int t = 0; t < m; ++t) {
            unsigned long long best = 0ull; int bestI = -1;
            for (int i = lane; i < cntB; i += 32) {
                unsigned long long k64 = ((unsigned long long)bk[i] << 32) | (unsigned)(0x7FFFFFFF - bi[i]);
                if (k64 > best) { best = k64; bestI = i; }
            }
#pragma unroll
            for (int off = 16; off; off >>= 1) {
                unsigned long long ob = __shfl_xor_sync(0xffffffffu, best, off);
                int oi = __shfl_xor_sync(0xffffffffu, bestI, off);
                if (ob > best) { best = ob; bestI = oi; }
            }
            if (lane == 0) {
                unsigned ku = bk[bestI];
                unsigned orig = (ku & 0x80000000u) ? (ku & 0x7FFFFFFFu) : ~ku;
                selVal[c0 + t] = __uint_as_float(orig);
                selIdx[c0 + t] = bi[bestI];
                bk[bestI] = 0u;             // below every real key
            }
            __syncwarp();
        }
    }
    __syncthreads();

    if (tid < KTOP) {
        float v = selVal[tid];
        float rs = v;
#pragma unroll
        for (int off = 16; off; off >>= 1) rs += __shfl_xor_sync(0xffffffffu, rs, off);
        rs += 1e-12f;
        bool msk = (v / rs) > 0.f;
        outIdx[(((size_t)p * V_ + q) * N_ + n) * KTOP + tid] = msk ? selIdx[tid] : -1;
    }
}

// ---------------- Vn column means ----------------
__global__ void meanv_part(const float* __restrict__ Vn, float* __restrict__ part)
{
    int v = blockIdx.x, s = blockIdx.y, d = threadIdx.x;
    int m0 = s * (N_ / 16);
    float acc = 0.f;
#pragma unroll 8
    for (int m = 0; m < N_ / 16; ++m)
        acc += Vn[((size_t)v * N_ + m0 + m) * D_ + d];
    part[((size_t)v * 16 + s) * D_ + d] = acc;
}

__global__ void meanv_reduce(const float* __restrict__ part, float* __restrict__ meanV)
{
    int v = blockIdx.x, d = threadIdx.x;
    float acc = 0.f;
#pragma unroll
    for (int s = 0; s < 16; ++s) acc += part[((size_t)v * 16 + s) * D_ + d];
    meanV[v * D_ + d] = acc * (1.0f / N_);
}

// ---------------- sparse neighbor attention + final fuse ----------------
__global__ void __launch_bounds__(256) nbr_final_kernel(
    const float* __restrict__ Qn, const float* __restrict__ Kn, const float* __restrict__ Vn,
    const float* __restrict__ meanV, const int* __restrict__ topIdx,
    const float* __restrict__ aligned, const float* __restrict__ Hin,
    const float* __restrict__ alpha_align, const float* __restrict__ beta,
    float* __restrict__ out)
{
    int n = blockIdx.x, p = blockIdx.y;
    int tid = threadIdx.x;
    int lane = tid & 31, warp = tid >> 5;

    __shared__ float qs[D_];
    __shared__ int   sidx[KTOP];
    __shared__ float sw[KTOP];
    __shared__ int   uniformFlag;

    qs[tid] = Qn[((size_t)p * N_ + n) * D_ + tid];
    float acc = meanV[p * D_ + tid];           // q == p: uniform softmax = mean of Vn[p]

    for (int qq = 0; qq < V_; ++qq) {
        if (qq == p) continue;
        __syncthreads();
        if (tid < KTOP) sidx[tid] = topIdx[(((size_t)p * V_ + qq) * N_ + n) * KTOP + tid];
        __syncthreads();

        {
            int i0 = sidx[warp], i1 = sidx[warp+8], i2 = sidx[warp+16], i3 = sidx[warp+24];
            const float* r0 = Kn + ((size_t)qq * N_ + (i0 >= 0 ? i0 : 0)) * D_;
            const float* r1 = Kn + ((size_t)qq * N_ + (i1 >= 0 ? i1 : 0)) * D_;
            const float* r2 = Kn + ((size_t)qq * N_ + (i2 >= 0 ? i2 : 0)) * D_;
            const float* r3 = Kn + ((size_t)qq * N_ + (i3 >= 0 ? i3 : 0)) * D_;
            float s0 = 0.f, s1 = 0.f, s2 = 0.f, s3 = 0.f;
#pragma unroll
            for (int c = 0; c < 8; ++c) {
                float qv = qs[c * 32 + lane];
                s0 = fmaf(qv, r0[c * 32 + lane], s0);
                s1 = fmaf(qv, r1[c * 32 + lane], s1);
                s2 = fmaf(qv, r2[c * 32 + lane], s2);
                s3 = fmaf(qv, r3[c * 32 + lane], s3);
            }
#pragma unroll
            for (int off = 16; off; off >>= 1) {
                s0 += __shfl_xor_sync(0xffffffffu, s0, off);
                s1 += __shfl_xor_sync(0xffffffffu, s1, off);
                s2 += __shfl_xor_sync(0xffffffffu, s2, off);
                s3 += __shfl_xor_sync(0xffffffffu, s3, off);
            }
            if (lane == 0) {
                sw[warp]      = (i0 >= 0) ? s0 * 0.0625f : -3.4e38f;
                sw[warp + 8]  = (i1 >= 0) ? s1 * 0.0625f : -3.4e38f;
                sw[warp + 16] = (i2 >= 0) ? s2 * 0.0625f : -3.4e38f;
                sw[warp + 24] = (i3 >= 0) ? s3 * 0.0625f : -3.4e38f;
            }
        }
        __syncthreads();

        if (warp == 0) {
            int id = sidx[lane];
            float s = sw[lane];
            unsigned validMask = __ballot_sync(0xffffffffu, id >= 0);
            float mx = (id >= 0) ? s : -3.4e38f;
#pragma unroll
            for (int off = 16; off; off >>= 1) mx = fmaxf(mx, __shfl_xor_sync(0xffffffffu, mx, off));
            float e = (id >= 0) ? expf(s - mx) : 0.f;
            float sum = e;
#pragma unroll
            for (int off = 16; off; off >>= 1) sum += __shfl_xor_sync(0xffffffffu, sum, off);
            sw[lane] = (validMask == 0u) ? 0.f : e / sum;
            if (lane == 0) uniformFlag = (validMask == 0u);
        }
        __syncthreads();

        if (uniformFlag) {
            acc += meanV[qq * D_ + tid];
        } else {
            float a0 = 0.f, a1 = 0.f, a2 = 0.f, a3 = 0.f;
#pragma unroll
            for (int j = 0; j < KTOP; j += 4) {
                int i0 = sidx[j], i1 = sidx[j+1], i2 = sidx[j+2], i3 = sidx[j+3];
                if (i0 >= 0) a0 = fmaf(sw[j],   Vn[((size_t)qq * N_ + i0) * D_ + tid], a0);
                if (i1 >= 0) a1 = fmaf(sw[j+1], Vn[((size_t)qq * N_ + i1) * D_ + tid], a1);
                if (i2 >= 0) a2 = fmaf(sw[j+2], Vn[((size_t)qq * N_ + i2) * D_ + tid], a2);
                if (i3 >= 0) a3 = fmaf(sw[j+3], Vn[((size_t)qq * N_ + i3) * D_ + tid], a3);
            }
            acc += (a0 + a1) + (a2 + a3);
        }
    }

    float al = aligned[((size_t)p * N_ + n) * D_ + tid];
    float a  = 1.f / (1.f + expf(-alpha_align[0]));
    float f  = fmaxf(a * al + (1.f - a) * acc, 0.f);
    float b  = beta[0];
    out[((size_t)p * N_ + n) * D_ + tid] =
        b * Hin[((size_t)p * N_ + n) * D_ + tid] + (1.f - b) * f;
}

// ---------------- launch ----------------
extern "C" void kernel_launch(void* const* d_in, const int* in_sizes, int n_in,
                              void* d_out, int out_size)
{
    const float* H      = (const float*)d_in[0];
    const float* C      = (const float*)d_in[1];
    const float* WQ     = (const float*)d_in[2];
    const float* WK     = (const float*)d_in[3];
    const float* WV     = (const float*)d_in[4];
    const float* ipw    = (const float*)d_in[5];
    const float* ipb    = (const float*)d_in[6];
    const float* opw    = (const float*)d_in[7];
    const float* opb    = (const float*)d_in[8];
    const float* alphas = (const float*)d_in[9];
    const float* aal    = (const float*)d_in[10];
    const float* beta   = (const float*)d_in[11];
    float* out = (float*)d_out;

    float *qkv, *o, *aligned, *Qn, *Kn, *Vn, *meanP, *meanV;
    int* idx;
    cudaGetSymbolAddress((void**)&qkv,     g_qkv);
    cudaGetSymbolAddress((void**)&o,       g_o);
    cudaGetSymbolAddress((void**)&aligned, g_aligned);
    cudaGetSymbolAddress((void**)&Qn,      g_Qn);
    cudaGetSymbolAddress((void**)&Kn,      g_Kn);
    cudaGetSymbolAddress((void**)&Vn,      g_Vn);
    cudaGetSymbolAddress((void**)&meanP,   g_meanPart);
    cudaGetSymbolAddress((void**)&meanV,   g_meanV);
    cudaGetSymbolAddress((void**)&idx,     g_idx);

    // top-k depends only on C
    topk_kernel<<<dim3(N_, 12), 128>>>(C, idx);

    // qkv = H @ in_proj_w^T + b            grid 12 x 96
    gemm64<0><<<dim3(E3_/BN, M_/BM, 1), 128>>>(H, ipw, nullptr, nullptr,
                                               qkv, nullptr, nullptr, ipb, nullptr, nullptr);

    // per-(n,h) 4x4 view attention
    attn_kernel<<<(N_*HEADS_)/8, 256>>>(qkv, o);

    // aligned = alphas*(o @ out_proj^T + b) + (1-alphas)*H     grid 4 x 96
    gemm64<1><<<dim3(D_/BN, M_/BM, 1), 128>>>(o, opw, nullptr, nullptr,
                                              aligned, nullptr, nullptr, opb, alphas, H);

    // fused Qn/Kn/Vn = per-view aligned @ {WQ,WK,WV}^T          grid 12 x 24 x 4
    gemm64<3><<<dim3(E3_/BN, N_/BM, V_), 128>>>(aligned, WQ, WK, WV,
                                                Qn, Kn, Vn, nullptr, nullptr, nullptr);

    // Vn column means
    meanv_part<<<dim3(V_, 16), 256>>>(Vn, meanP);
    meanv_reduce<<<V_, 256>>>(meanP, meanV);

    // sparse neighbor attention + final fusion
    nbr_final_kernel<<<dim3(N_, V_), 256>>>(Qn, Kn, Vn, meanV, idx, aligned, H, aal, beta, out);
}

// round 10
// speedup vs baseline: 2.6565x; 1.1768x over previous
#include <cuda_runtime.h>
#include <cuda_bf16.h>
#include <math.h>

#define V_ 4
#define N_ 1536
#define D_ 256
#define HEADS_ 4
#define DH_ 64
#define KTOP 32
#define M_ (V_*N_)    /* 6144 */
#define E3_ (3*D_)    /* 768  */

// ---------------- scratch ----------------
__device__ float g_qkv[M_*E3_];
__device__ float g_o[M_*D_];
__device__ float g_aligned[M_*D_];
__device__ float g_Qn[M_*D_];
__device__ float g_Kn[M_*D_];
__device__ float g_Vn[M_*D_];
__device__ float g_meanPart[V_*16*D_];
__device__ float g_meanV[V_*D_];
__device__ int   g_idx[V_*V_*N_*KTOP];

// ---------------- bf16-split tensor-core NT GEMM ----------------
// C[m,e] = sum_k A[m,k]*B[e,k], K=256. fp32 operands split hi/lo bf16;
// acc = Ah*Bh + Ah*Bl + Al*Bh (fp32 accumulate). |err| <~ 2^-18 per product.
// MODE 0: O0 = acc + bias (E=768)
// MODE 1: O0 = alphas[v]*(acc+bias) + (1-alphas[v])*H (E=256)
// MODE 3: fused QKV per view z: eBase segment selects {B0,B1,B2}->{O0,O1,O2}
#define TBM 64
#define TBN 64
#define TBK 32
#define TKIT (D_/TBK)   /* 8 */
#define SSTR 40         /* smem row stride in bf16 */

__device__ __forceinline__ void mma16816(float* d, const unsigned* a, const unsigned* b)
{
    asm volatile(
        "mma.sync.aligned.m16n8k16.row.col.f32.bf16.bf16.f32 "
        "{%0,%1,%2,%3}, {%4,%5,%6,%7}, {%8,%9}, {%0,%1,%2,%3};"
        : "+f"(d[0]), "+f"(d[1]), "+f"(d[2]), "+f"(d[3])
        : "r"(a[0]), "r"(a[1]), "r"(a[2]), "r"(a[3]), "r"(b[0]), "r"(b[1]));
}

template<int MODE>
__global__ void __launch_bounds__(128) gemmTC(
    const float* __restrict__ A, const float* __restrict__ B0,
    const float* __restrict__ B1, const float* __restrict__ B2,
    float* __restrict__ O0, float* __restrict__ O1, float* __restrict__ O2,
    const float* __restrict__ bias, const float* __restrict__ alphas,
    const float* __restrict__ Hin)
{
    __shared__ __nv_bfloat16 Ah[2][TBM][SSTR], Al[2][TBM][SSTR];
    __shared__ __nv_bfloat16 Bh[2][TBN][SSTR], Bl[2][TBN][SSTR];

    const int tid  = threadIdx.x;
    const int lane = tid & 31;
    const int warp = tid >> 5;
    const int wr = warp & 1;        // m half
    const int wc = warp >> 1;       // n half
    const int mBase = blockIdx.y * TBM;
    const int eBase = blockIdx.x * TBN;
    const int z = blockIdx.z;

    const float* Ap = A;
    const float* Bp = B0;
    int eLoc = eBase;
    int seg = 0;
    if (MODE == 3) {
        Ap = A + (size_t)z * N_ * D_;
        seg = eBase >> 8;
        Bp = (seg == 0 ? B0 : (seg == 1 ? B1 : B2)) + (size_t)z * D_ * D_;
        eLoc = eBase & 255;
    }

    // global load pattern: 512 float4 per tile, 4 per thread
    const int gr4 = tid >> 3;        // base row group
    const int gc4 = tid & 7;         // float4 col within 32-wide k slab

    float4 fa[4], fb[4];
#pragma unroll
    for (int it = 0; it < 4; ++it) {
        int row = (tid + it * 128) >> 3;
        int c4  = (tid + it * 128) & 7;
        fa[it] = *reinterpret_cast<const float4*>(Ap + (size_t)(mBase + row) * D_ + c4 * 4);
        fb[it] = *reinterpret_cast<const float4*>(Bp + (size_t)(eLoc  + row) * D_ + c4 * 4);
    }

    // convert + store helper (lambda-free)
#define CVT_STORE(BUF)                                                            \
    {                                                                             \
        _Pragma("unroll")                                                         \
        for (int it = 0; it < 4; ++it) {                                          \
            int row = (tid + it * 128) >> 3;                                      \
            int col = ((tid + it * 128) & 7) * 4;                                 \
            float va[4] = {fa[it].x, fa[it].y, fa[it].z, fa[it].w};               \
            float vb[4] = {fb[it].x, fb[it].y, fb[it].z, fb[it].w};               \
            __nv_bfloat162 ah2, al2, bh2, bl2;                                    \
            _Pragma("unroll")                                                     \
            for (int g = 0; g < 2; ++g) {                                         \
                __nv_bfloat16 h0 = __float2bfloat16(va[g*2+0]);                   \
                __nv_bfloat16 h1 = __float2bfloat16(va[g*2+1]);                   \
                __nv_bfloat16 l0 = __float2bfloat16(va[g*2+0] - __bfloat162float(h0)); \
                __nv_bfloat16 l1 = __float2bfloat16(va[g*2+1] - __bfloat162float(h1)); \
                ah2.x = h0; ah2.y = h1; al2.x = l0; al2.y = l1;                   \
                *reinterpret_cast<__nv_bfloat162*>(&Ah[BUF][row][col + g*2]) = ah2; \
                *reinterpret_cast<__nv_bfloat162*>(&Al[BUF][row][col + g*2]) = al2; \
                h0 = __float2bfloat16(vb[g*2+0]);                                 \
                h1 = __float2bfloat16(vb[g*2+1]);                                 \
                l0 = __float2bfloat16(vb[g*2+0] - __bfloat162float(h0));          \
                l1 = __float2bfloat16(vb[g*2+1] - __bfloat162float(h1));          \
                bh2.x = h0; bh2.y = h1; bl2.x = l0; bl2.y = l1;                   \
                *reinterpret_cast<__nv_bfloat162*>(&Bh[BUF][row][col + g*2]) = bh2; \
                *reinterpret_cast<__nv_bfloat162*>(&Bl[BUF][row][col + g*2]) = bl2; \
            }                                                                     \
        }                                                                         \
    }

    CVT_STORE(0)
    __syncthreads();

    float acc[2][4][4];
#pragma unroll
    for (int i = 0; i < 2; ++i)
#pragma unroll
        for (int j = 0; j < 4; ++j)
#pragma unroll
            for (int c = 0; c < 4; ++c) acc[i][j][c] = 0.f;

    const int fgr = lane >> 2;           // fragment row 0..7
    const int fck = (lane & 3) * 2;      // fragment k-pair col

    int buf = 0;
    for (int t = 0; t < TKIT; ++t) {
        if (t + 1 < TKIT) {
            int kk = (t + 1) * TBK;
#pragma unroll
            for (int it = 0; it < 4; ++it) {
                int row = (tid + it * 128) >> 3;
                int c4  = (tid + it * 128) & 7;
                fa[it] = *reinterpret_cast<const float4*>(Ap + (size_t)(mBase + row) * D_ + kk + c4 * 4);
                fb[it] = *reinterpret_cast<const float4*>(Bp + (size_t)(eLoc  + row) * D_ + kk + c4 * 4);
            }
        }
#pragma unroll
        for (int kb = 0; kb < TBK; kb += 16) {
            unsigned afh[2][4], afl[2][4], bfh[4][2], bfl[4][2];
#pragma unroll
            for (int mt = 0; mt < 2; ++mt) {
                int r0 = wr * 32 + mt * 16 + fgr;
                afh[mt][0] = *reinterpret_cast<const unsigned*>(&Ah[buf][r0    ][kb + fck]);
                afh[mt][1] = *reinterpret_cast<const unsigned*>(&Ah[buf][r0 + 8][kb + fck]);
                afh[mt][2] = *reinterpret_cast<const unsigned*>(&Ah[buf][r0    ][kb + fck + 8]);
                afh[mt][3] = *reinterpret_cast<const unsigned*>(&Ah[buf][r0 + 8][kb + fck + 8]);
                afl[mt][0] = *reinterpret_cast<const unsigned*>(&Al[buf][r0    ][kb + fck]);
                afl[mt][1] = *reinterpret_cast<const unsigned*>(&Al[buf][r0 + 8][kb + fck]);
                afl[mt][2] = *reinterpret_cast<const unsigned*>(&Al[buf][r0    ][kb + fck + 8]);
                afl[mt][3] = *reinterpret_cast<const unsigned*>(&Al[buf][r0 + 8][kb + fck + 8]);
            }
#pragma unroll
            for (int nt = 0; nt < 4; ++nt) {
                int r0 = wc * 32 + nt * 8 + fgr;
                bfh[nt][0] = *reinterpret_cast<const unsigned*>(&Bh[buf][r0][kb + fck]);
                bfh[nt][1] = *reinterpret_cast<const unsigned*>(&Bh[buf][r0][kb + fck + 8]);
                bfl[nt][0] = *reinterpret_cast<const unsigned*>(&Bl[buf][r0][kb + fck]);
                bfl[nt][1] = *reinterpret_cast<const unsigned*>(&Bl[buf][r0][kb + fck + 8]);
            }
#pragma unroll
            for (int mt = 0; mt < 2; ++mt)
#pragma unroll
                for (int nt = 0; nt < 4; ++nt) {
                    mma16816(acc[mt][nt], afh[mt], bfh[nt]);
                    mma16816(acc[mt][nt], afh[mt], bfl[nt]);
                    mma16816(acc[mt][nt], afl[mt], bfh[nt]);
                }
        }
        if (t + 1 < TKIT) {
            int nb = buf ^ 1;
            CVT_STORE(nb)
            __syncthreads();
            buf = nb;
        }
    }

    // ---- epilogue ----
    const int cn = (lane & 3) * 2;
#pragma unroll
    for (int mt = 0; mt < 2; ++mt) {
#pragma unroll
        for (int nt = 0; nt < 4; ++nt) {
#pragma unroll
            for (int half = 0; half < 2; ++half) {
                int row = mBase + wr * 32 + mt * 16 + fgr + half * 8;
                int col = eBase + wc * 32 + nt * 8 + cn;
                float v0 = acc[mt][nt][half * 2 + 0];
                float v1 = acc[mt][nt][half * 2 + 1];
                if (MODE == 0) {
                    v0 += bias[col]; v1 += bias[col + 1];
                    float2 st = {v0, v1};
                    *reinterpret_cast<float2*>(&O0[(size_t)row * E3_ + col]) = st;
                } else if (MODE == 1) {
                    int v = row / N_;
                    float al = alphas[v];
                    v0 = al * (v0 + bias[col])     + (1.f - al) * Hin[(size_t)row * D_ + col];
                    v1 = al * (v1 + bias[col + 1]) + (1.f - al) * Hin[(size_t)row * D_ + col + 1];
                    float2 st = {v0, v1};
                    *reinterpret_cast<float2*>(&O0[(size_t)row * D_ + col]) = st;
                } else {
                    int colLoc = col & 255;
                    float* Op = (seg == 0) ? O0 : (seg == 1 ? O1 : O2);
                    float2 st = {v0, v1};
                    *reinterpret_cast<float2*>(&Op[((size_t)z * N_ + row) * D_ + colLoc]) = st;
                }
            }
        }
    }
#undef CVT_STORE
}

// ---------------- per-(n,h) 4x4 view attention ----------------
__global__ void attn_kernel(const float* __restrict__ qkv, float* __restrict__ o)
{
    int gw = (blockIdx.x * blockDim.x + threadIdx.x) >> 5;
    int lane = threadIdx.x & 31;
    if (gw >= N_ * HEADS_) return;
    int n = gw >> 2;
    int h = gw & 3;

    float q[4][2], k[4][2], v[4][2];
#pragma unroll
    for (int s = 0; s < 4; ++s) {
        size_t base = ((size_t)s * N_ + n) * E3_ + h * DH_ + lane;
        q[s][0] = qkv[base];          q[s][1] = qkv[base + 32];
        k[s][0] = qkv[base + D_];     k[s][1] = qkv[base + D_ + 32];
        v[s][0] = qkv[base + 2*D_];   v[s][1] = qkv[base + 2*D_ + 32];
    }
    float att[4][4];
#pragma unroll
    for (int s = 0; s < 4; ++s)
#pragma unroll
        for (int t = 0; t < 4; ++t) {
            float p = q[s][0]*k[t][0] + q[s][1]*k[t][1];
#pragma unroll
            for (int off = 16; off; off >>= 1) p += __shfl_xor_sync(0xffffffffu, p, off);
            att[s][t] = p * 0.125f;
        }
#pragma unroll
    for (int s = 0; s < 4; ++s) {
        float mx = fmaxf(fmaxf(att[s][0], att[s][1]), fmaxf(att[s][2], att[s][3]));
        float e0 = expf(att[s][0] - mx), e1 = expf(att[s][1] - mx);
        float e2 = expf(att[s][2] - mx), e3 = expf(att[s][3] - mx);
        float inv = 1.f / (e0 + e1 + e2 + e3);
        float w0 = e0*inv, w1 = e1*inv, w2 = e2*inv, w3 = e3*inv;
        float o0 = w0*v[0][0] + w1*v[1][0] + w2*v[2][0] + w3*v[3][0];
        float o1 = w0*v[0][1] + w1*v[1][1] + w2*v[2][1] + w3*v[3][1];
        size_t ob = ((size_t)s * N_ + n) * D_ + h * DH_ + lane;
        o[ob] = o0; o[ob + 32] = o1;
    }
}

// ---------------- top-32 via radix select ----------------
__global__ void __launch_bounds__(128) topk_kernel(const float* __restrict__ C, int* __restrict__ outIdx)
{
    int n = blockIdx.x;
    int pid = blockIdx.y;
    int p = pid / 3;
    int qo = pid % 3;
    int q = qo + (qo >= p ? 1 : 0);
    const float* row = C + (((size_t)p * V_ + q) * N_ + n) * (size_t)N_;

    __shared__ int      hist[4096];
    __shared__ unsigned bk[N_];
    __shared__ int      bi[N_];
    __shared__ int      gsum[128];
    __shared__ int      tcnt[128];
    __shared__ int      selIdx[KTOP];
    __shared__ float    selVal[KTOP];
    __shared__ int      thrInfo[3];
    __shared__ int      bcnt;

    int tid = threadIdx.x, lane = tid & 31, warp = tid >> 5;

    float4 t0 = *reinterpret_cast<const float4*>(row + (size_t)(tid)       * 4);
    float4 t1 = *reinterpret_cast<const float4*>(row + (size_t)(tid + 128) * 4);
    float4 t2 = *reinterpret_cast<const float4*>(row + (size_t)(tid + 256) * 4);

#pragma unroll
    for (int i = 0; i < 32; ++i) hist[tid + i * 128] = 0;
    if (tid == 0) bcnt = 0;
    __syncthreads();

    unsigned key[12];
    {
        float vv[12] = {t0.x, t0.y, t0.z, t0.w, t1.x, t1.y, t1.z, t1.w, t2.x, t2.y, t2.z, t2.w};
#pragma unroll
        for (int j = 0; j < 12; ++j) {
            unsigned u = __float_as_uint(vv[j]);
            key[j] = (u & 0x80000000u) ? ~u : (u | 0x80000000u);
        }
    }
#pragma unroll
    for (int j = 0; j < 12; ++j) atomicAdd(&hist[key[j] >> 20], 1);
    __syncthreads();

    {
        int g = tid;
        int hiBin = 4095 - 32 * g;
        int s = 0;
#pragma unroll
        for (int i = 0; i < 32; ++i) {
            int off = (i + g) & 31;
            s += hist[hiBin - off];
        }
        gsum[g] = s;
    }
    __syncthreads();

    if (warp == 0) {
        int a[4];
#pragma unroll
        for (int j = 0; j < 4; ++j) a[j] = gsum[lane * 4 + j];
        int psum = a[0] + a[1] + a[2] + a[3];
        int sc = psum;
#pragma unroll
        for (int off = 1; off < 32; off <<= 1) {
            int t = __shfl_up_sync(0xffffffffu, sc, off);
            if (lane >= off) sc += t;
        }
        int excl = sc - psum;
        unsigned bal = __ballot_sync(0xffffffffu, excl + psum >= KTOP);
        int L = __ffs(bal) - 1;
        if (lane == L) {
            int running = excl;
            int gg = 0;
#pragma unroll
            for (; gg < 4; ++gg) {
                if (running + a[gg] >= KTOP) break;
                running += a[gg];
            }
            int G = lane * 4 + gg;
            int hiBin = 4095 - 32 * G;
            int b = hiBin - 31;
            for (int i = 0; i < 32; ++i) {
                int bin = hiBin - i;
                int c = hist[bin];
                if (running + c >= KTOP) { b = bin; break; }
                running += c;
            }
            thrInfo[0] = b; thrInfo[1] = running; thrInfo[2] = KTOP - running;
        }
    }
    __syncthreads();

    const int b = thrInfo[0];

    int cnt = 0;
#pragma unroll
    for (int j = 0; j < 12; ++j) {
        unsigned bin = key[j] >> 20;
        if ((int)bin > b) cnt++;
        else if ((int)bin == b) {
            int gi = (j < 4) ? (tid * 4 + j) : ((j < 8) ? ((tid + 128) * 4 + j - 4) : ((tid + 256) * 4 + j - 8));
            int pos = atomicAdd(&bcnt, 1);
            bk[pos] = key[j];
            bi[pos] = gi;
        }
    }
    tcnt[tid] = cnt;
    __syncthreads();

    if (tid == 0) {
        int r = 0;
        for (int t = 0; t < 128; ++t) { int c = tcnt[t]; tcnt[t] = r; r += c; }
    }
    __syncthreads();

    {
        int w = tcnt[tid];
#pragma unroll
        for (int j = 0; j < 12; ++j) {
            if ((int)(key[j] >> 20) > b) {
                int gi = (j < 4) ? (tid * 4 + j) : ((j < 8) ? ((tid + 128) * 4 + j - 4) : ((tid + 256) * 4 + j - 8));
                unsigned ku = key[j];
                unsigned orig = (ku & 0x80000000u) ? (ku & 0x7FFFFFFFu) : ~ku;
                selIdx[w] = gi;
                selVal[w] = __uint_as_float(orig);
                w++;
            }
        }
    }
    __syncthreads();

    if (warp == 0) {
        int c0 = thrInfo[1], m = thrInfo[2];
        int cntB = bcnt;
        for (int t = 0; t < m; ++t) {
            unsigned long long best = 0ull; int bestI = -1;
            for (int i = lane; i < cntB; i += 32) {
                unsigned long long k64 = ((unsigned long long)bk[i] << 32) | (unsigned)(0x7FFFFFFF - bi[i]);
                if (k64 > best) { best = k64; bestI = i; }
            }
#pragma unroll
            for (int off = 16; off; off >>= 1) {
                unsigned long long ob = __shfl_xor_sync(0xffffffffu, best, off);
                int oi = __shfl_xor_sync(0xffffffffu, bestI, off);
                if (ob > best) { best = ob; bestI = oi; }
            }
            if (lane == 0) {
                unsigned ku = bk[bestI];
                unsigned orig = (ku & 0x80000000u) ? (ku & 0x7FFFFFFFu) : ~ku;
                selVal[c0 + t] = __uint_as_float(orig);
                selIdx[c0 + t] = bi[bestI];
                bk[bestI] = 0u;
            }
            __syncwarp();
        }
    }
    __syncthreads();

    if (tid < KTOP) {
        float v = selVal[tid];
        float rs = v;
#pragma unroll
        for (int off = 16; off; off >>= 1) rs += __shfl_xor_sync(0xffffffffu, rs, off);
        rs += 1e-12f;
        bool msk = (v / rs) > 0.f;
        outIdx[(((size_t)p * V_ + q) * N_ + n) * KTOP + tid] = msk ? selIdx[tid] : -1;
    }
}

// ---------------- Vn column means ----------------
__global__ void meanv_part(const float* __restrict__ Vn, float* __restrict__ part)
{
    int v = blockIdx.x, s = blockIdx.y, d = threadIdx.x;
    int m0 = s * (N_ / 16);
    float acc = 0.f;
#pragma unroll 8
    for (int m = 0; m < N_ / 16; ++m)
        acc += Vn[((size_t)v * N_ + m0 + m) * D_ + d];
    part[((size_t)v * 16 + s) * D_ + d] = acc;
}

__global__ void meanv_reduce(const float* __restrict__ part, float* __restrict__ meanV)
{
    int v = blockIdx.x, d = threadIdx.x;
    float acc = 0.f;
#pragma unroll
    for (int s = 0; s < 16; ++s) acc += part[((size_t)v * 16 + s) * D_ + d];
    meanV[v * D_ + d] = acc * (1.0f / N_);
}

// ---------------- sparse neighbor attention + final fuse ----------------
__global__ void __launch_bounds__(256) nbr_final_kernel(
    const float* __restrict__ Qn, const float* __restrict__ Kn, const float* __restrict__ Vn,
    const float* __restrict__ meanV, const int* __restrict__ topIdx,
    const float* __restrict__ aligned, const float* __restrict__ Hin,
    const float* __restrict__ alpha_align, const float* __restrict__ beta,
    float* __restrict__ out)
{
    int n = blockIdx.x, p = blockIdx.y;
    int tid = threadIdx.x;
    int lane = tid & 31, warp = tid >> 5;

    __shared__ float qs[D_];
    __shared__ int   sidx[KTOP];
    __shared__ float sw[KTOP];
    __shared__ int   uniformFlag;

    qs[tid] = Qn[((size_t)p * N_ + n) * D_ + tid];
    float acc = meanV[p * D_ + tid];

    for (int qq = 0; qq < V_; ++qq) {
        if (qq == p) continue;
        __syncthreads();
        if (tid < KTOP) sidx[tid] = topIdx[(((size_t)p * V_ + qq) * N_ + n) * KTOP + tid];
        __syncthreads();

        {
            int i0 = sidx[warp], i1 = sidx[warp+8], i2 = sidx[warp+16], i3 = sidx[warp+24];
            const float* r0 = Kn + ((size_t)qq * N_ + (i0 >= 0 ? i0 : 0)) * D_;
            const float* r1 = Kn + ((size_t)qq * N_ + (i1 >= 0 ? i1 : 0)) * D_;
            const float* r2 = Kn + ((size_t)qq * N_ + (i2 >= 0 ? i2 : 0)) * D_;
            const float* r3 = Kn + ((size_t)qq * N_ + (i3 >= 0 ? i3 : 0)) * D_;
            float s0 = 0.f, s1 = 0.f, s2 = 0.f, s3 = 0.f;
#pragma unroll
            for (int c = 0; c < 8; ++c) {
                float qv = qs[c * 32 + lane];
                s0 = fmaf(qv, r0[c * 32 + lane], s0);
                s1 = fmaf(qv, r1[c * 32 + lane], s1);
                s2 = fmaf(qv, r2[c * 32 + lane], s2);
                s3 = fmaf(qv, r3[c * 32 + lane], s3);
            }
#pragma unroll
            for (int off = 16; off; off >>= 1) {
                s0 += __shfl_xor_sync(0xffffffffu, s0, off);
                s1 += __shfl_xor_sync(0xffffffffu, s1, off);
                s2 += __shfl_xor_sync(0xffffffffu, s2, off);
                s3 += __shfl_xor_sync(0xffffffffu, s3, off);
            }
            if (lane == 0) {
                sw[warp]      = (i0 >= 0) ? s0 * 0.0625f : -3.4e38f;
                sw[warp + 8]  = (i1 >= 0) ? s1 * 0.0625f : -3.4e38f;
                sw[warp + 16] = (i2 >= 0) ? s2 * 0.0625f : -3.4e38f;
                sw[warp + 24] = (i3 >= 0) ? s3 * 0.0625f : -3.4e38f;
            }
        }
        __syncthreads();

        if (warp == 0) {
            int id = sidx[lane];
            float s = sw[lane];
            unsigned validMask = __ballot_sync(0xffffffffu, id >= 0);
            float mx = (id >= 0) ? s : -3.4e38f;
#pragma unroll
            for (int off = 16; off; off >>= 1) mx = fmaxf(mx, __shfl_xor_sync(0xffffffffu, mx, off));
            float e = (id >= 0) ? expf(s - mx) : 0.f;
            float sum = e;
#pragma unroll
            for (int off = 16; off; off >>= 1) sum += __shfl_xor_sync(0xffffffffu, sum, off);
            sw[lane] = (validMask == 0u) ? 0.f : e / sum;
            if (lane == 0) uniformFlag = (validMask == 0u);
        }
        __syncthreads();

        if (uniformFlag) {
            acc += meanV[qq * D_ + tid];
        } else {
            float a0 = 0.f, a1 = 0.f, a2 = 0.f, a3 = 0.f;
#pragma unroll
            for (int j = 0; j < KTOP; j += 4) {
                int i0 = sidx[j], i1 = sidx[j+1], i2 = sidx[j+2], i3 = sidx[j+3];
                if (i0 >= 0) a0 = fmaf(sw[j],   Vn[((size_t)qq * N_ + i0) * D_ + tid], a0);
                if (i1 >= 0) a1 = fmaf(sw[j+1], Vn[((size_t)qq * N_ + i1) * D_ + tid], a1);
                if (i2 >= 0) a2 = fmaf(sw[j+2], Vn[((size_t)qq * N_ + i2) * D_ + tid], a2);
                if (i3 >= 0) a3 = fmaf(sw[j+3], Vn[((size_t)qq * N_ + i3) * D_ + tid], a3);
            }
            acc += (a0 + a1) + (a2 + a3);
        }
    }

    float al = aligned[((size_t)p * N_ + n) * D_ + tid];
    float a  = 1.f / (1.f + expf(-alpha_align[0]));
    float f  = fmaxf(a * al + (1.f - a) * acc, 0.f);
    float b  = beta[0];
    out[((size_t)p * N_ + n) * D_ + tid] =
        b * Hin[((size_t)p * N_ + n) * D_ + tid] + (1.f - b) * f;
}

// ---------------- launch ----------------
extern "C" void kernel_launch(void* const* d_in, const int* in_sizes, int n_in,
                              void* d_out, int out_size)
{
    const float* H      = (const float*)d_in[0];
    const float* C      = (const float*)d_in[1];
    const float* WQ     = (const float*)d_in[2];
    const float* WK     = (const float*)d_in[3];
    const float* WV     = (const float*)d_in[4];
    const float* ipw    = (const float*)d_in[5];
    const float* ipb    = (const float*)d_in[6];
    const float* opw    = (const float*)d_in[7];
    const float* opb    = (const float*)d_in[8];
    const float* alphas = (const float*)d_in[9];
    const float* aal    = (const float*)d_in[10];
    const float* beta   = (const float*)d_in[11];
    float* out = (float*)d_out;

    float *qkv, *o, *aligned, *Qn, *Kn, *Vn, *meanP, *meanV;
    int* idx;
    cudaGetSymbolAddress((void**)&qkv,     g_qkv);
    cudaGetSymbolAddress((void**)&o,       g_o);
    cudaGetSymbolAddress((void**)&aligned, g_aligned);
    cudaGetSymbolAddress((void**)&Qn,      g_Qn);
    cudaGetSymbolAddress((void**)&Kn,      g_Kn);
    cudaGetSymbolAddress((void**)&Vn,      g_Vn);
    cudaGetSymbolAddress((void**)&meanP,   g_meanPart);
    cudaGetSymbolAddress((void**)&meanV,   g_meanV);
    cudaGetSymbolAddress((void**)&idx,     g_idx);

    // top-k depends only on C
    topk_kernel<<<dim3(N_, 12), 128>>>(C, idx);

    // qkv = H @ in_proj_w^T + b            grid 12 x 96
    gemmTC<0><<<dim3(E3_/TBN, M_/TBM, 1), 128>>>(H, ipw, nullptr, nullptr,
                                                 qkv, nullptr, nullptr, ipb, nullptr, nullptr);

    // per-(n,h) 4x4 view attention
    attn_kernel<<<(N_*HEADS_)/8, 256>>>(qkv, o);

    // aligned = alphas*(o @ out_proj^T + b) + (1-alphas)*H     grid 4 x 96
    gemmTC<1><<<dim3(D_/TBN, M_/TBM, 1), 128>>>(o, opw, nullptr, nullptr,
                                                aligned, nullptr, nullptr, opb, alphas, H);

    // fused Qn/Kn/Vn = per-view aligned @ {WQ,WK,WV}^T          grid 12 x 24 x 4
    gemmTC<3><<<dim3(E3_/TBN, N_/TBM, V_), 128>>>(aligned, WQ, WK, WV,
                                                  Qn, Kn, Vn, nullptr, nullptr, nullptr);

    // Vn column means
    meanv_part<<<dim3(V_, 16), 256>>>(Vn, meanP);
    meanv_reduce<<<V_, 256>>>(meanP, meanV);

    // sparse neighbor attention + final fusion
    nbr_final_kernel<<<dim3(N_, V_), 256>>>(Qn, Kn, Vn, meanV, idx, aligned, H, aal, beta, out);
}